// round 7
// baseline (speedup 1.0000x reference)
#include <cuda_runtime.h>
#include <cstdint>

// ---------------------------------------------------------------------------
// Problem constants
// ---------------------------------------------------------------------------
#define BATCH  4
#define SEQ    2048
#define DMODEL 1024

// Scratch (device globals: allocation-free). Pre-split operand storage.
__device__ float g_Qh[(size_t)BATCH * SEQ * DMODEL];
__device__ float g_Ql[(size_t)BATCH * SEQ * DMODEL];
__device__ float g_Kh[(size_t)BATCH * SEQ * DMODEL];
__device__ float g_Kl[(size_t)BATCH * SEQ * DMODEL];
__device__ float g_Vt[(size_t)BATCH * SEQ * DMODEL];
__device__ float g_S [(size_t)BATCH * SEQ * SEQ];
__device__ float g_Ph[(size_t)BATCH * SEQ * SEQ];
__device__ float g_Pl[(size_t)BATCH * SEQ * SEQ];

// ---------------------------------------------------------------------------
// Helpers
// ---------------------------------------------------------------------------
__device__ __forceinline__ uint32_t smem_u32(const void* p) {
    uint32_t a;
    asm("{ .reg .u64 t; cvta.to.shared.u64 t, %1; cvt.u32.u64 %0, t; }"
        : "=r"(a) : "l"(p));
    return a;
}

#define CP_ASYNC16(saddr, gptr) \
    asm volatile("cp.async.cg.shared.global [%0], [%1], 16;" \
        :: "r"(saddr), "l"(gptr) : "memory")
#define CP_COMMIT() asm volatile("cp.async.commit_group;" ::: "memory")
#define CP_WAIT0()  asm volatile("cp.async.wait_group 0;" ::: "memory")
#define CP_WAIT1()  asm volatile("cp.async.wait_group 1;" ::: "memory")

// tf32x3 split: hi = top 10 mantissa bits (valid tf32), lo = rounded residual
__device__ __forceinline__ void split3(float x, uint32_t& hi, uint32_t& lo) {
    const uint32_t h = __float_as_uint(x) & 0xffffe000u;
    hi = h;
    const float l = x - __uint_as_float(h);
    uint32_t lt;
    asm("cvt.rna.tf32.f32 %0, %1;" : "=r"(lt) : "f"(l));
    lo = lt;
}

__device__ __forceinline__ uint32_t to_tf32(float x) {
    uint32_t t;
    asm("cvt.rna.tf32.f32 %0, %1;" : "=r"(t) : "f"(x));
    return t;
}

// D += A(16x8 tf32) * B(8x8 tf32), fp32 accumulate
__device__ __forceinline__ void mma8(float* d, const uint32_t* a, const uint32_t* b) {
    asm volatile(
        "mma.sync.aligned.m16n8k8.row.col.f32.tf32.tf32.f32 "
        "{%0,%1,%2,%3}, {%4,%5,%6,%7}, {%8,%9}, {%0,%1,%2,%3};"
        : "+f"(d[0]), "+f"(d[1]), "+f"(d[2]), "+f"(d[3])
        : "r"(a[0]), "r"(a[1]), "r"(a[2]), "r"(a[3]), "r"(b[0]), "r"(b[1]));
}

// ===========================================================================
// 1) Projection GEMM (dynamic split; B = W is MN-major -> transpose load)
//    SCHEME=3: x3 (Q,K paths)  SCHEME=2: x2, B rounded (V path)
//    EPI=1: write split hi->C, lo->C2   EPI=2: write rna-tf32(val)->C
// ===========================================================================
#define A_TILE_F 4608            // 128 * 36 floats
#define B_TILE_F 4608            // 32 * 136 padded fits (4352) -> keep 4608
#define STAGE_F  (A_TILE_F + B_TILE_F)
#define PROJ_SMEM_BYTES (2 * STAGE_F * 4)

template <int SCHEME, int EPI>
__device__ __forceinline__
void proj_body(const float* __restrict__ A, const float* __restrict__ B,
               const float* __restrict__ bias, float* __restrict__ C,
               float* __restrict__ C2)
{
    extern __shared__ float smem[];
    const int K = DMODEL, lda = DMODEL, ldb = DMODEL, ldc = DMODEL;

    const int tid  = threadIdx.x;
    const int wid  = tid >> 5;
    const int lane = tid & 31;
    const int tg   = lane >> 2;
    const int tk   = lane & 3;
    const int row0 = blockIdx.y * 128;
    const int col0 = blockIdx.x * 128;
    const int wm   = (wid >> 2) * 64;
    const int wn   = (wid & 3) * 32;

    float acc[4][4][4];
#pragma unroll
    for (int mt = 0; mt < 4; mt++)
#pragma unroll
        for (int nt = 0; nt < 4; nt++)
#pragma unroll
            for (int e = 0; e < 4; e++) acc[mt][nt][e] = 0.0f;

    auto fill = [&](int st, int k0) {
        float* base = smem + st * STAGE_F;
        const uint32_t sAa = smem_u32(base);
        const uint32_t sBa = smem_u32(base + A_TILE_F);
#pragma unroll
        for (int j = 0; j < 4; j++) {
            const int idx = tid + j * 256;
            const int r  = idx >> 3;
            const int c4 = (idx & 7) << 2;
            CP_ASYNC16(sAa + (uint32_t)(r * 36 + c4) * 4u,
                       A + (size_t)(row0 + r) * lda + k0 + c4);
        }
#pragma unroll
        for (int j = 0; j < 4; j++) {
            const int idx = tid + j * 256;
            const int kk = idx >> 5;
            const int n4 = (idx & 31) << 2;
            CP_ASYNC16(sBa + (uint32_t)(kk * 136 + n4) * 4u,
                       B + (size_t)(k0 + kk) * ldb + col0 + n4);
        }
        CP_COMMIT();
    };

    auto compute = [&](int st) {
        const float* sA = smem + st * STAGE_F;
        const float* sB = sA + A_TILE_F;
#pragma unroll
        for (int s = 0; s < 4; s++) {
            uint32_t bh[4][2], bl[4][2];
#pragma unroll
            for (int nt = 0; nt < 4; nt++) {
                const int n0 = wn + nt * 8;
                const float b0 = sB[(s * 8 + tk)     * 136 + n0 + tg];
                const float b1 = sB[(s * 8 + tk + 4) * 136 + n0 + tg];
                if (SCHEME == 3) {
                    split3(b0, bh[nt][0], bl[nt][0]);
                    split3(b1, bh[nt][1], bl[nt][1]);
                } else {
                    bh[nt][0] = to_tf32(b0);
                    bh[nt][1] = to_tf32(b1);
                }
            }
#pragma unroll
            for (int mt = 0; mt < 4; mt++) {
                const int m0 = wm + mt * 16;
                uint32_t ah[4], al[4];
                split3(sA[(m0 + tg)     * 36 + s * 8 + tk],     ah[0], al[0]);
                split3(sA[(m0 + tg + 8) * 36 + s * 8 + tk],     ah[1], al[1]);
                split3(sA[(m0 + tg)     * 36 + s * 8 + tk + 4], ah[2], al[2]);
                split3(sA[(m0 + tg + 8) * 36 + s * 8 + tk + 4], ah[3], al[3]);
#pragma unroll
                for (int nt = 0; nt < 4; nt++) {
                    mma8(acc[mt][nt], ah, bh[nt]);
                    if (SCHEME == 3) mma8(acc[mt][nt], ah, bl[nt]);
                    mma8(acc[mt][nt], al, bh[nt]);
                }
            }
        }
    };

    const int nchunk = K >> 5;
    fill(0, 0);
    for (int i = 0; i < nchunk; i++) {
        if (i + 1 < nchunk) { fill((i + 1) & 1, (i + 1) << 5); CP_WAIT1(); }
        else                { CP_WAIT0(); }
        __syncthreads();
        compute(i & 1);
        __syncthreads();
    }

    // epilogue
#pragma unroll
    for (int mt = 0; mt < 4; mt++) {
        const int r = row0 + wm + mt * 16 + tg;
#pragma unroll
        for (int nt = 0; nt < 4; nt++) {
            const int col = col0 + wn + nt * 8 + tk * 2;
            const float b0 = bias[col], b1 = bias[col + 1];
            float v[4];
            v[0] = acc[mt][nt][0] + b0;
            v[1] = acc[mt][nt][1] + b1;
            v[2] = acc[mt][nt][2] + b0;
            v[3] = acc[mt][nt][3] + b1;
            const size_t o0 = (size_t)r * ldc + col;
            const size_t o1 = (size_t)(r + 8) * ldc + col;
            if (EPI == 1) {
                uint32_t h[4], l[4];
#pragma unroll
                for (int e = 0; e < 4; e++) split3(v[e], h[e], l[e]);
                *(float2*)(C  + o0) = make_float2(__uint_as_float(h[0]), __uint_as_float(h[1]));
                *(float2*)(C  + o1) = make_float2(__uint_as_float(h[2]), __uint_as_float(h[3]));
                *(float2*)(C2 + o0) = make_float2(__uint_as_float(l[0]), __uint_as_float(l[1]));
                *(float2*)(C2 + o1) = make_float2(__uint_as_float(l[2]), __uint_as_float(l[3]));
            } else {
                *(float2*)(C + o0) = make_float2(__uint_as_float(to_tf32(v[0])),
                                                 __uint_as_float(to_tf32(v[1])));
                *(float2*)(C + o1) = make_float2(__uint_as_float(to_tf32(v[2])),
                                                 __uint_as_float(to_tf32(v[3])));
            }
        }
    }
}

// Q (z=0) and K (z=1) projections: x3, split epilogue
__global__ __launch_bounds__(256, 2)
void proj_qk_k(const float* __restrict__ q, const float* __restrict__ k,
               const float* __restrict__ Wq, const float* __restrict__ bq,
               const float* __restrict__ Wk, const float* __restrict__ bk,
               float* __restrict__ Qh, float* __restrict__ Ql,
               float* __restrict__ Kh, float* __restrict__ Kl)
{
    if (blockIdx.z == 0) proj_body<3, 1>(q, Wq, bq, Qh, Ql);
    else                 proj_body<3, 1>(k, Wk, bk, Kh, Kl);
}

// V projection: x2 (Wv rounded), rounded-tf32 epilogue
__global__ __launch_bounds__(256, 2)
void proj_v_k(const float* __restrict__ v,
              const float* __restrict__ Wv, const float* __restrict__ bv,
              float* __restrict__ Vt)
{
    proj_body<2, 2>(v, Wv, bv, Vt, nullptr);
}

// ===========================================================================
// 2) Scores GEMM: pre-split operands, x3, conversion-free mainloop.
//    S = alpha * Q @ K^T. A tiles from (Qh,Ql), B tiles from (Kh,Kl),
//    both [rows][K] k-contiguous. KC=16, 2-stage.
// ===========================================================================
#define S_PAD     20
#define S_TILE_F  (128 * S_PAD)        // 2560
#define S_STAGE_F (4 * S_TILE_F)       // 10240
#define SCORES_SMEM_BYTES (2 * S_STAGE_F * 4)   // 81920

__global__ __launch_bounds__(256, 2)
void scores_k(const float* __restrict__ Qh_, const float* __restrict__ Ql_,
              const float* __restrict__ Kh_, const float* __restrict__ Kl_,
              float* __restrict__ Sg, float alpha)
{
    extern __shared__ float smem[];
    const long long zo = (long long)blockIdx.z * SEQ * DMODEL;
    const float* __restrict__ Ah = Qh_ + zo;
    const float* __restrict__ Al = Ql_ + zo;
    const float* __restrict__ Bh = Kh_ + zo;
    const float* __restrict__ Bl = Kl_ + zo;
    float* __restrict__ C = Sg + (long long)blockIdx.z * SEQ * SEQ;

    const int tid  = threadIdx.x;
    const int wid  = tid >> 5;
    const int lane = tid & 31;
    const int tg   = lane >> 2;
    const int tk   = lane & 3;
    const int row0 = blockIdx.y * 128;
    const int col0 = blockIdx.x * 128;
    const int wm   = (wid >> 2) * 64;
    const int wn   = (wid & 3) * 32;

    float acc[4][4][4];
#pragma unroll
    for (int mt = 0; mt < 4; mt++)
#pragma unroll
        for (int nt = 0; nt < 4; nt++)
#pragma unroll
            for (int e = 0; e < 4; e++) acc[mt][nt][e] = 0.0f;

    // stage tiles: [0]=Ah [1]=Al [2]=Bh [3]=Bl, each 128 x 20 floats
    auto fill = [&](int st, int k0) {
        float* base = smem + st * S_STAGE_F;
        const uint32_t a0 = smem_u32(base);
        const uint32_t a1 = a0 + S_TILE_F * 4;
        const uint32_t a2 = a1 + S_TILE_F * 4;
        const uint32_t a3 = a2 + S_TILE_F * 4;
#pragma unroll
        for (int j = 0; j < 2; j++) {
            const int idx = tid + j * 256;        // 0..511
            const int r  = idx >> 2;              // 0..127
            const int c4 = (idx & 3) << 2;        // 0,4,8,12
            const uint32_t so = (uint32_t)(r * S_PAD + c4) * 4u;
            const size_t  goA = (size_t)(row0 + r) * DMODEL + k0 + c4;
            const size_t  goB = (size_t)(col0 + r) * DMODEL + k0 + c4;
            CP_ASYNC16(a0 + so, Ah + goA);
            CP_ASYNC16(a1 + so, Al + goA);
            CP_ASYNC16(a2 + so, Bh + goB);
            CP_ASYNC16(a3 + so, Bl + goB);
        }
        CP_COMMIT();
    };

    auto compute = [&](int st) {
        const uint32_t* sAh = (const uint32_t*)(smem + st * S_STAGE_F);
        const uint32_t* sAl = sAh + S_TILE_F;
        const uint32_t* sBh = sAl + S_TILE_F;
        const uint32_t* sBl = sBh + S_TILE_F;
#pragma unroll
        for (int s = 0; s < 2; s++) {
            uint32_t bh[4][2], bl[4][2];
#pragma unroll
            for (int nt = 0; nt < 4; nt++) {
                const int n0 = wn + nt * 8;
                const int i0 = (n0 + tg) * S_PAD + s * 8 + tk;
                bh[nt][0] = sBh[i0];
                bh[nt][1] = sBh[i0 + 4];
                bl[nt][0] = sBl[i0];
                bl[nt][1] = sBl[i0 + 4];
            }
#pragma unroll
            for (int mt = 0; mt < 4; mt++) {
                const int m0 = wm + mt * 16;
                const int i0 = (m0 + tg) * S_PAD + s * 8 + tk;
                const int i1 = i0 + 8 * S_PAD;
                uint32_t ah[4], al[4];
                ah[0] = sAh[i0];     al[0] = sAl[i0];
                ah[1] = sAh[i1];     al[1] = sAl[i1];
                ah[2] = sAh[i0 + 4]; al[2] = sAl[i0 + 4];
                ah[3] = sAh[i1 + 4]; al[3] = sAl[i1 + 4];
#pragma unroll
                for (int nt = 0; nt < 4; nt++) {
                    mma8(acc[mt][nt], ah, bh[nt]);
                    mma8(acc[mt][nt], ah, bl[nt]);
                    mma8(acc[mt][nt], al, bh[nt]);
                }
            }
        }
    };

    const int nchunk = DMODEL >> 4;    // 64
    fill(0, 0);
    for (int i = 0; i < nchunk; i++) {
        if (i + 1 < nchunk) { fill((i + 1) & 1, (i + 1) << 4); CP_WAIT1(); }
        else                { CP_WAIT0(); }
        __syncthreads();
        compute(i & 1);
        __syncthreads();
    }

#pragma unroll
    for (int mt = 0; mt < 4; mt++) {
        const int r = row0 + wm + mt * 16 + tg;
#pragma unroll
        for (int nt = 0; nt < 4; nt++) {
            const int col = col0 + wn + nt * 8 + tk * 2;
            float2 v0, v1;
            v0.x = acc[mt][nt][0] * alpha;
            v0.y = acc[mt][nt][1] * alpha;
            v1.x = acc[mt][nt][2] * alpha;
            v1.y = acc[mt][nt][3] * alpha;
            *(float2*)(C + (size_t)r * SEQ + col)       = v0;
            *(float2*)(C + (size_t)(r + 8) * SEQ + col) = v1;
        }
    }
}

// ===========================================================================
// 3) Softmax + threefry dropout; writes split P (Ph, Pl)
// ===========================================================================
__device__ __forceinline__ uint32_t threefry_mask_word(uint32_t idx)
{
    const uint32_t ks0 = 0u;
    const uint32_t ks1 = 42u;
    const uint32_t ks2 = 42u ^ 0x1BD11BDAu;
    uint32_t x0 = ks0;
    uint32_t x1 = idx + ks1;
#define TFR(r) { x0 += x1; x1 = __funnelshift_l(x1, x1, (r)); x1 ^= x0; }
    TFR(13) TFR(15) TFR(26) TFR(6)
    x0 += ks1; x1 += ks2 + 1u;
    TFR(17) TFR(29) TFR(16) TFR(24)
    x0 += ks2; x1 += ks0 + 2u;
    TFR(13) TFR(15) TFR(26) TFR(6)
    x0 += ks0; x1 += ks1 + 3u;
    TFR(17) TFR(29) TFR(16) TFR(24)
    x0 += ks1; x1 += ks2 + 4u;
    TFR(13) TFR(15) TFR(26) TFR(6)
    x0 += ks2; x1 += ks0 + 5u;
#undef TFR
    return x0 ^ x1;
}

__global__ __launch_bounds__(256, 4)
void softmax_dropout_k(const float* __restrict__ S,
                       float* __restrict__ Ph, float* __restrict__ Pl)
{
    const int q   = blockIdx.x;
    const int b   = blockIdx.y;
    const int tid = threadIdx.x;
    const size_t ro = ((size_t)b * SEQ + q) * SEQ;
    const float* __restrict__ row = S + ro;

    float a[8];
#pragma unroll
    for (int j = 0; j < 8; j++) a[j] = row[tid + j * 256];

    float m = a[0];
#pragma unroll
    for (int j = 1; j < 8; j++) m = fmaxf(m, a[j]);
#pragma unroll
    for (int s = 16; s > 0; s >>= 1)
        m = fmaxf(m, __shfl_xor_sync(0xffffffffu, m, s));
    __shared__ float red[8];
    const int wid = tid >> 5, lane = tid & 31;
    if (lane == 0) red[wid] = m;
    __syncthreads();
    m = red[0];
#pragma unroll
    for (int w = 1; w < 8; w++) m = fmaxf(m, red[w]);
    __syncthreads();

    float s0 = 0.0f;
#pragma unroll
    for (int j = 0; j < 8; j++) {
        a[j] = __expf(a[j] - m);
        s0 += a[j];
    }
#pragma unroll
    for (int s = 16; s > 0; s >>= 1)
        s0 += __shfl_xor_sync(0xffffffffu, s0, s);
    if (lane == 0) red[wid] = s0;
    __syncthreads();
    s0 = 0.0f;
#pragma unroll
    for (int w = 0; w < 8; w++) s0 += red[w];

    const float inv = 2.0f / s0;   // dropout 1/(1-p)=2 folded in

    const uint32_t base = ((uint32_t)(b * SEQ + q)) * (uint32_t)SEQ;
#pragma unroll
    for (int j = 0; j < 8; j++) {
        const uint32_t k = (uint32_t)tid + (uint32_t)j * 256u;
        const uint32_t w = threefry_mask_word(base + k);
        const float val = (w >> 31) ? 0.0f : a[j] * inv;
        uint32_t h, l;
        split3(val, h, l);
        Ph[ro + k] = __uint_as_float(h);
        Pl[ro + k] = __uint_as_float(l);
    }
}

// ===========================================================================
// 4) PV GEMM: A = pre-split P (Ph,Pl), B = pre-rounded Vt (MN-major, trans
//    load). x2, conversion-free. KC=32, 2-stage.
// ===========================================================================
#define PV_A_F     4608                 // 128 * 36
#define PV_B_F     4352                 // 32 * 136
#define PV_STAGE_F (2 * PV_A_F + PV_B_F)   // 13568
#define PV_SMEM_BYTES (2 * PV_STAGE_F * 4) // 108544

__global__ __launch_bounds__(256, 2)
void pv_k(const float* __restrict__ Ph_, const float* __restrict__ Pl_,
          const float* __restrict__ Vt_, float* __restrict__ Og)
{
    extern __shared__ float smem[];
    const float* __restrict__ Ah = Ph_ + (long long)blockIdx.z * SEQ * SEQ;
    const float* __restrict__ Al = Pl_ + (long long)blockIdx.z * SEQ * SEQ;
    const float* __restrict__ Bt = Vt_ + (long long)blockIdx.z * SEQ * DMODEL;
    float* __restrict__ C = Og + (long long)blockIdx.z * SEQ * DMODEL;

    const int tid  = threadIdx.x;
    const int wid  = tid >> 5;
    const int lane = tid & 31;
    const int tg   = lane >> 2;
    const int tk   = lane & 3;
    const int row0 = blockIdx.y * 128;
    const int col0 = blockIdx.x * 128;
    const int wm   = (wid >> 2) * 64;
    const int wn   = (wid & 3) * 32;

    float acc[4][4][4];
#pragma unroll
    for (int mt = 0; mt < 4; mt++)
#pragma unroll
        for (int nt = 0; nt < 4; nt++)
#pragma unroll
            for (int e = 0; e < 4; e++) acc[mt][nt][e] = 0.0f;

    // stage: Ah[128][36], Al[128][36], Bt[32][136]
    auto fill = [&](int st, int k0) {
        float* base = smem + st * PV_STAGE_F;
        const uint32_t aH = smem_u32(base);
        const uint32_t aL = aH + PV_A_F * 4;
        const uint32_t aB = aL + PV_A_F * 4;
#pragma unroll
        for (int j = 0; j < 4; j++) {
            const int idx = tid + j * 256;
            const int r  = idx >> 3;
            const int c4 = (idx & 7) << 2;
            const uint32_t so = (uint32_t)(r * 36 + c4) * 4u;
            const size_t  go = (size_t)(row0 + r) * SEQ + k0 + c4;
            CP_ASYNC16(aH + so, Ah + go);
            CP_ASYNC16(aL + so, Al + go);
        }
#pragma unroll
        for (int j = 0; j < 4; j++) {
            const int idx = tid + j * 256;
            const int kk = idx >> 5;
            const int n4 = (idx & 31) << 2;
            CP_ASYNC16(aB + (uint32_t)(kk * 136 + n4) * 4u,
                       Bt + (size_t)(k0 + kk) * DMODEL + col0 + n4);
        }
        CP_COMMIT();
    };

    auto compute = [&](int st) {
        const uint32_t* sAh = (const uint32_t*)(smem + st * PV_STAGE_F);
        const uint32_t* sAl = sAh + PV_A_F;
        const uint32_t* sB  = sAl + PV_A_F;
#pragma unroll
        for (int s = 0; s < 4; s++) {
            uint32_t bt[4][2];
#pragma unroll
            for (int nt = 0; nt < 4; nt++) {
                const int n0 = wn + nt * 8;
                bt[nt][0] = sB[(s * 8 + tk)     * 136 + n0 + tg];
                bt[nt][1] = sB[(s * 8 + tk + 4) * 136 + n0 + tg];
            }
#pragma unroll
            for (int mt = 0; mt < 4; mt++) {
                const int m0 = wm + mt * 16;
                const int i0 = (m0 + tg) * 36 + s * 8 + tk;
                const int i1 = i0 + 8 * 36;
                uint32_t ah[4], al[4];
                ah[0] = sAh[i0];     al[0] = sAl[i0];
                ah[1] = sAh[i1];     al[1] = sAl[i1];
                ah[2] = sAh[i0 + 4]; al[2] = sAl[i0 + 4];
                ah[3] = sAh[i1 + 4]; al[3] = sAl[i1 + 4];
#pragma unroll
                for (int nt = 0; nt < 4; nt++) {
                    mma8(acc[mt][nt], ah, bt[nt]);
                    mma8(acc[mt][nt], al, bt[nt]);
                }
            }
        }
    };

    const int nchunk = SEQ >> 5;   // 64
    fill(0, 0);
    for (int i = 0; i < nchunk; i++) {
        if (i + 1 < nchunk) { fill((i + 1) & 1, (i + 1) << 5); CP_WAIT1(); }
        else                { CP_WAIT0(); }
        __syncthreads();
        compute(i & 1);
        __syncthreads();
    }

#pragma unroll
    for (int mt = 0; mt < 4; mt++) {
        const int r = row0 + wm + mt * 16 + tg;
#pragma unroll
        for (int nt = 0; nt < 4; nt++) {
            const int col = col0 + wn + nt * 8 + tk * 2;
            *(float2*)(C + (size_t)r * DMODEL + col) =
                make_float2(acc[mt][nt][0], acc[mt][nt][1]);
            *(float2*)(C + (size_t)(r + 8) * DMODEL + col) =
                make_float2(acc[mt][nt][2], acc[mt][nt][3]);
        }
    }
}

// ---------------------------------------------------------------------------
// Launcher
// ---------------------------------------------------------------------------
extern "C" void kernel_launch(void* const* d_in, const int* in_sizes, int n_in,
                              void* d_out, int out_size)
{
    (void)in_sizes; (void)n_in; (void)out_size;
    const float* query = (const float*)d_in[0];
    const float* key_  = (const float*)d_in[1];
    const float* value = (const float*)d_in[2];
    const float* Wq    = (const float*)d_in[3];
    const float* bq    = (const float*)d_in[4];
    const float* Wk    = (const float*)d_in[5];
    const float* bk    = (const float*)d_in[6];
    const float* Wv    = (const float*)d_in[7];
    const float* bv    = (const float*)d_in[8];
    float* out = (float*)d_out;

    float *dQh, *dQl, *dKh, *dKl, *dVt, *dS, *dPh, *dPl;
    cudaGetSymbolAddress((void**)&dQh, g_Qh);
    cudaGetSymbolAddress((void**)&dQl, g_Ql);
    cudaGetSymbolAddress((void**)&dKh, g_Kh);
    cudaGetSymbolAddress((void**)&dKl, g_Kl);
    cudaGetSymbolAddress((void**)&dVt, g_Vt);
    cudaGetSymbolAddress((void**)&dS,  g_S);
    cudaGetSymbolAddress((void**)&dPh, g_Ph);
    cudaGetSymbolAddress((void**)&dPl, g_Pl);

    static bool attr_done = false;
    if (!attr_done) {
        cudaFuncSetAttribute(proj_qk_k,
                             cudaFuncAttributeMaxDynamicSharedMemorySize, PROJ_SMEM_BYTES);
        cudaFuncSetAttribute(proj_v_k,
                             cudaFuncAttributeMaxDynamicSharedMemorySize, PROJ_SMEM_BYTES);
        cudaFuncSetAttribute(scores_k,
                             cudaFuncAttributeMaxDynamicSharedMemorySize, SCORES_SMEM_BYTES);
        cudaFuncSetAttribute(pv_k,
                             cudaFuncAttributeMaxDynamicSharedMemorySize, PV_SMEM_BYTES);
        attr_done = true;
    }

    dim3 thr(256);

    // 1) Projections: Q,K (x3, split outputs) + V (x2, rounded output)
    dim3 gQK(DMODEL / 128, (BATCH * SEQ) / 128, 2);
    proj_qk_k<<<gQK, thr, PROJ_SMEM_BYTES>>>(query, key_, Wq, bq, Wk, bk,
                                             dQh, dQl, dKh, dKl);
    dim3 gV(DMODEL / 128, (BATCH * SEQ) / 128, 1);
    proj_v_k<<<gV, thr, PROJ_SMEM_BYTES>>>(value, Wv, bv, dVt);

    // 2) Scores: S = 8 * Q @ K^T (pre-split x3)
    dim3 gScore(SEQ / 128, SEQ / 128, BATCH);
    scores_k<<<gScore, thr, SCORES_SMEM_BYTES>>>(dQh, dQl, dKh, dKl, dS, 8.0f);

    // 3) Softmax + threefry dropout -> split P
    dim3 gSm(SEQ, BATCH, 1);
    softmax_dropout_k<<<gSm, thr>>>(dS, dPh, dPl);

    // 4) Output: O = P @ Vt (pre-split x2)
    dim3 gOut(DMODEL / 128, SEQ / 128, BATCH);
    pv_k<<<gOut, thr, PV_SMEM_BYTES>>>(dPh, dPl, dVt, out);
}

// round 8
// speedup vs baseline: 1.1354x; 1.1354x over previous
#include <cuda_runtime.h>
#include <cstdint>

// ---------------------------------------------------------------------------
// Problem constants
// ---------------------------------------------------------------------------
#define BATCH  4
#define SEQ    2048
#define DMODEL 1024

// Scratch (device globals: allocation-free)
__device__ float g_Q[(size_t)BATCH * SEQ * DMODEL];
__device__ float g_K[(size_t)BATCH * SEQ * DMODEL];
__device__ float g_V[(size_t)BATCH * SEQ * DMODEL];
__device__ float g_S[(size_t)BATCH * SEQ * SEQ];

// ---------------------------------------------------------------------------
// Helpers
// ---------------------------------------------------------------------------
__device__ __forceinline__ uint32_t smem_u32(const void* p) {
    uint32_t a;
    asm("{ .reg .u64 t; cvta.to.shared.u64 t, %1; cvt.u32.u64 %0, t; }"
        : "=r"(a) : "l"(p));
    return a;
}

#define CP_ASYNC16(saddr, gptr) \
    asm volatile("cp.async.cg.shared.global [%0], [%1], 16;" \
        :: "r"(saddr), "l"(gptr) : "memory")
#define CP_COMMIT() asm volatile("cp.async.commit_group;" ::: "memory")
#define CP_WAIT0()  asm volatile("cp.async.wait_group 0;" ::: "memory")
#define CP_WAIT1()  asm volatile("cp.async.wait_group 1;" ::: "memory")

// tf32x3 split WITHOUT cvt: hi = top-10-mantissa truncation (valid tf32);
// lo passed as raw fp32 bits — the HMMA tf32 datapath uses only the tf32
// bit subset, so this is hardware truncation of lo (error ~2^-21 |x|,
// same order as the x3 scheme's intrinsic residuals). Saves the 20-cyc CVT
// on every fragment in the hot loops.
__device__ __forceinline__ void split3(float x, uint32_t& hi, uint32_t& lo) {
    const uint32_t h = __float_as_uint(x) & 0xffffe000u;
    hi = h;
    lo = __float_as_uint(x - __uint_as_float(h));
}

// Proper rna rounding (for x2-scheme B operand, where rounding quality is
// first-order)
__device__ __forceinline__ uint32_t to_tf32(float x) {
    uint32_t t;
    asm("cvt.rna.tf32.f32 %0, %1;" : "=r"(t) : "f"(x));
    return t;
}

// D += A(16x8 tf32) * B(8x8 tf32), fp32 accumulate
__device__ __forceinline__ void mma8(float* d, const uint32_t* a, const uint32_t* b) {
    asm volatile(
        "mma.sync.aligned.m16n8k8.row.col.f32.tf32.tf32.f32 "
        "{%0,%1,%2,%3}, {%4,%5,%6,%7}, {%8,%9}, {%0,%1,%2,%3};"
        : "+f"(d[0]), "+f"(d[1]), "+f"(d[2]), "+f"(d[3])
        : "r"(a[0]), "r"(a[1]), "r"(a[2]), "r"(a[3]), "r"(b[0]), "r"(b[1]));
}

// ---------------------------------------------------------------------------
// tf32 emulated GEMM body: C[m,n] = alpha * sum_k A[m,k]*Bmat[k,n] (+ bias[n])
//   TRANSB_LOAD=false: Bmat[k,n] = B[n*ldb + k]  (B K-major [N,K], e.g. K^T)
//   TRANSB_LOAD=true : Bmat[k,n] = B[k*ldb + n]  (B MN-major [K,N], e.g. W, V)
//   SCHEME=3: D += Ah*Bh + Ah*Bl + Al*Bh   (fp32-accurate)
//   SCHEME=2: D += Ah*Bt + Al*Bt           (A exact, B rounded rna ~2^-12)
// BM=BN=128, KC=32, 256 threads (8 warps, each 64x32), cp.async 2-stage.
// ---------------------------------------------------------------------------
#define A_TILE_F 4608            // 128 * 36 floats
#define B_TILE_F 4608            // >= max(128*36 direct, 32*136 trans)
#define STAGE_F  (A_TILE_F + B_TILE_F)
#define GEMM_SMEM_BYTES (2 * STAGE_F * 4)

template <bool TRANSB_LOAD, bool HASBIAS, int SCHEME>
__device__ __forceinline__
void gemm_body(const float* __restrict__ A, const float* __restrict__ B,
               const float* __restrict__ bias, float* __restrict__ C,
               int K, int lda, int ldb, int ldc, float alpha)
{
    extern __shared__ float smem[];

    const int tid  = threadIdx.x;
    const int wid  = tid >> 5;
    const int lane = tid & 31;
    const int tg   = lane >> 2;      // 0..7
    const int tk   = lane & 3;       // 0..3
    const int row0 = blockIdx.y * 128;
    const int col0 = blockIdx.x * 128;
    const int wm   = (wid >> 2) * 64;   // warp m-offset in tile
    const int wn   = (wid & 3) * 32;    // warp n-offset in tile

    float acc[4][4][4];
#pragma unroll
    for (int mt = 0; mt < 4; mt++)
#pragma unroll
        for (int nt = 0; nt < 4; nt++)
#pragma unroll
            for (int e = 0; e < 4; e++) acc[mt][nt][e] = 0.0f;

    // ---- stage fill via cp.async ----
    auto fill = [&](int st, int k0) {
        float* base = smem + st * STAGE_F;
        const uint32_t sAa = smem_u32(base);
        const uint32_t sBa = smem_u32(base + A_TILE_F);
        // A tile: [128 m][32 k], k-contiguous global
#pragma unroll
        for (int j = 0; j < 4; j++) {
            const int idx = tid + j * 256;
            const int r  = idx >> 3;
            const int c4 = (idx & 7) << 2;
            CP_ASYNC16(sAa + (uint32_t)(r * 36 + c4) * 4u,
                       A + (size_t)(row0 + r) * lda + k0 + c4);
        }
        if (TRANSB_LOAD) {
            // B global [K,N] n-contiguous -> smem [32 k][128 n], ld=136
#pragma unroll
            for (int j = 0; j < 4; j++) {
                const int idx = tid + j * 256;
                const int kk = idx >> 5;
                const int n4 = (idx & 31) << 2;
                CP_ASYNC16(sBa + (uint32_t)(kk * 136 + n4) * 4u,
                           B + (size_t)(k0 + kk) * ldb + col0 + n4);
            }
        } else {
            // B global [N,K] k-contiguous -> smem [128 n][32 k], ld=36
#pragma unroll
            for (int j = 0; j < 4; j++) {
                const int idx = tid + j * 256;
                const int r  = idx >> 3;
                const int c4 = (idx & 7) << 2;
                CP_ASYNC16(sBa + (uint32_t)(r * 36 + c4) * 4u,
                           B + (size_t)(col0 + r) * ldb + k0 + c4);
            }
        }
        CP_COMMIT();
    };

    // ---- compute one staged chunk (4 k8-steps), register-lean order ----
    auto compute = [&](int st) {
        const float* sA = smem + st * STAGE_F;
        const float* sB = sA + A_TILE_F;
#pragma unroll
        for (int s = 0; s < 4; s++) {
            // B fragments for all 4 nt
            uint32_t bh[4][2], bl[4][2];
#pragma unroll
            for (int nt = 0; nt < 4; nt++) {
                const int n0 = wn + nt * 8;
                float b0, b1;
                if (TRANSB_LOAD) {
                    b0 = sB[(s * 8 + tk)     * 136 + n0 + tg];
                    b1 = sB[(s * 8 + tk + 4) * 136 + n0 + tg];
                } else {
                    b0 = sB[(n0 + tg) * 36 + s * 8 + tk];
                    b1 = sB[(n0 + tg) * 36 + s * 8 + tk + 4];
                }
                if (SCHEME == 3) {
                    split3(b0, bh[nt][0], bl[nt][0]);
                    split3(b1, bh[nt][1], bl[nt][1]);
                } else {
                    bh[nt][0] = to_tf32(b0);
                    bh[nt][1] = to_tf32(b1);
                }
            }
            // A fragments per mt
#pragma unroll
            for (int mt = 0; mt < 4; mt++) {
                const int m0 = wm + mt * 16;
                uint32_t ah[4], al[4];
                split3(sA[(m0 + tg)     * 36 + s * 8 + tk],     ah[0], al[0]);
                split3(sA[(m0 + tg + 8) * 36 + s * 8 + tk],     ah[1], al[1]);
                split3(sA[(m0 + tg)     * 36 + s * 8 + tk + 4], ah[2], al[2]);
                split3(sA[(m0 + tg + 8) * 36 + s * 8 + tk + 4], ah[3], al[3]);
#pragma unroll
                for (int nt = 0; nt < 4; nt++) {
                    mma8(acc[mt][nt], ah, bh[nt]);
                    if (SCHEME == 3) mma8(acc[mt][nt], ah, bl[nt]);
                    mma8(acc[mt][nt], al, bh[nt]);
                }
            }
        }
    };

    const int nchunk = K >> 5;   // K/32
    fill(0, 0);
    for (int i = 0; i < nchunk; i++) {
        if (i + 1 < nchunk) { fill((i + 1) & 1, (i + 1) << 5); CP_WAIT1(); }
        else                { CP_WAIT0(); }
        __syncthreads();
        compute(i & 1);
        __syncthreads();
    }

    // ---- epilogue ----
#pragma unroll
    for (int mt = 0; mt < 4; mt++) {
        const int r = row0 + wm + mt * 16 + tg;
#pragma unroll
        for (int nt = 0; nt < 4; nt++) {
            const int col = col0 + wn + nt * 8 + tk * 2;
            float2 v0, v1;
            v0.x = acc[mt][nt][0] * alpha;
            v0.y = acc[mt][nt][1] * alpha;
            v1.x = acc[mt][nt][2] * alpha;
            v1.y = acc[mt][nt][3] * alpha;
            if (HASBIAS) {
                const float b0 = bias[col], b1 = bias[col + 1];
                v0.x += b0; v0.y += b1;
                v1.x += b0; v1.y += b1;
            }
            *(float2*)(C + (size_t)r * ldc + col)       = v0;
            *(float2*)(C + (size_t)(r + 8) * ldc + col) = v1;
        }
    }
}

// Generic batched GEMM kernel (2 CTAs/SM)
template <bool TRANSB_LOAD, bool HASBIAS, int SCHEME>
__global__ __launch_bounds__(256, 2)
void mma_gemm_k(const float* __restrict__ Ag, const float* __restrict__ Bg,
                const float* __restrict__ bias, float* __restrict__ Cg,
                int K, int lda, int ldb, int ldc, float alpha,
                long long sA, long long sB, long long sC)
{
    const int z = blockIdx.z;
    gemm_body<TRANSB_LOAD, HASBIAS, SCHEME>(Ag + (long long)z * sA,
                                            Bg + (long long)z * sB,
                                            bias, Cg + (long long)z * sC,
                                            K, lda, ldb, ldc, alpha);
}

// Fused Q/K/V projection: blockIdx.z picks which projection.
// Q,K at x3 (feed the precision-critical score path); V at x2 (Wv rounded,
// error enters output linearly ~1e-4).
__global__ __launch_bounds__(256, 2)
void mma_proj3_k(const float* __restrict__ q, const float* __restrict__ k,
                 const float* __restrict__ v,
                 const float* __restrict__ Wq, const float* __restrict__ bq,
                 const float* __restrict__ Wk, const float* __restrict__ bk,
                 const float* __restrict__ Wv, const float* __restrict__ bv,
                 float* __restrict__ Q, float* __restrict__ K, float* __restrict__ V)
{
    if (blockIdx.z == 0)
        gemm_body<true, true, 3>(q, Wq, bq, Q, DMODEL, DMODEL, DMODEL, DMODEL, 1.0f);
    else if (blockIdx.z == 1)
        gemm_body<true, true, 3>(k, Wk, bk, K, DMODEL, DMODEL, DMODEL, DMODEL, 1.0f);
    else
        gemm_body<true, true, 2>(v, Wv, bv, V, DMODEL, DMODEL, DMODEL, DMODEL, 1.0f);
}

// ---------------------------------------------------------------------------
// JAX threefry2x32, key (0,42), partitionable scheme:
//   bits[i] = y0 ^ y1 of threefry2x32(key, (0, i)); keep <=> MSB==0
// ---------------------------------------------------------------------------
__device__ __forceinline__ uint32_t threefry_mask_word(uint32_t idx)
{
    const uint32_t ks0 = 0u;
    const uint32_t ks1 = 42u;
    const uint32_t ks2 = 42u ^ 0x1BD11BDAu;
    uint32_t x0 = ks0;
    uint32_t x1 = idx + ks1;
#define TFR(r) { x0 += x1; x1 = __funnelshift_l(x1, x1, (r)); x1 ^= x0; }
    TFR(13) TFR(15) TFR(26) TFR(6)
    x0 += ks1; x1 += ks2 + 1u;
    TFR(17) TFR(29) TFR(16) TFR(24)
    x0 += ks2; x1 += ks0 + 2u;
    TFR(13) TFR(15) TFR(26) TFR(6)
    x0 += ks0; x1 += ks1 + 3u;
    TFR(17) TFR(29) TFR(16) TFR(24)
    x0 += ks1; x1 += ks2 + 4u;
    TFR(13) TFR(15) TFR(26) TFR(6)
    x0 += ks2; x1 += ks0 + 5u;
#undef TFR
    return x0 ^ x1;
}

// ---------------------------------------------------------------------------
// Softmax + dropout, one block per (b,q) row of S. kept value scaled by 2.
// ---------------------------------------------------------------------------
__global__ __launch_bounds__(256, 4)
void softmax_dropout_k(float* __restrict__ S)
{
    const int q   = blockIdx.x;
    const int b   = blockIdx.y;
    const int tid = threadIdx.x;
    float* __restrict__ row = S + ((size_t)b * SEQ + q) * SEQ;

    float a[8];
#pragma unroll
    for (int j = 0; j < 8; j++) a[j] = row[tid + j * 256];

    float m = a[0];
#pragma unroll
    for (int j = 1; j < 8; j++) m = fmaxf(m, a[j]);
#pragma unroll
    for (int s = 16; s > 0; s >>= 1)
        m = fmaxf(m, __shfl_xor_sync(0xffffffffu, m, s));
    __shared__ float red[8];
    const int wid = tid >> 5, lane = tid & 31;
    if (lane == 0) red[wid] = m;
    __syncthreads();
    m = red[0];
#pragma unroll
    for (int w = 1; w < 8; w++) m = fmaxf(m, red[w]);
    __syncthreads();

    float s0 = 0.0f;
#pragma unroll
    for (int j = 0; j < 8; j++) {
        a[j] = __expf(a[j] - m);
        s0 += a[j];
    }
#pragma unroll
    for (int s = 16; s > 0; s >>= 1)
        s0 += __shfl_xor_sync(0xffffffffu, s0, s);
    if (lane == 0) red[wid] = s0;
    __syncthreads();
    s0 = 0.0f;
#pragma unroll
    for (int w = 0; w < 8; w++) s0 += red[w];

    const float inv = 2.0f / s0;

    const uint32_t base = ((uint32_t)(b * SEQ + q)) * (uint32_t)SEQ;
#pragma unroll
    for (int j = 0; j < 8; j++) {
        const uint32_t k = (uint32_t)tid + (uint32_t)j * 256u;
        const uint32_t w = threefry_mask_word(base + k);
        row[k] = (w >> 31) ? 0.0f : a[j] * inv;
    }
}

// ---------------------------------------------------------------------------
// Launcher
// ---------------------------------------------------------------------------
extern "C" void kernel_launch(void* const* d_in, const int* in_sizes, int n_in,
                              void* d_out, int out_size)
{
    (void)in_sizes; (void)n_in; (void)out_size;
    const float* query = (const float*)d_in[0];
    const float* key_  = (const float*)d_in[1];
    const float* value = (const float*)d_in[2];
    const float* Wq    = (const float*)d_in[3];
    const float* bq    = (const float*)d_in[4];
    const float* Wk    = (const float*)d_in[5];
    const float* bk    = (const float*)d_in[6];
    const float* Wv    = (const float*)d_in[7];
    const float* bv    = (const float*)d_in[8];
    float* out = (float*)d_out;

    float *dQ, *dK, *dV, *dS;
    cudaGetSymbolAddress((void**)&dQ, g_Q);
    cudaGetSymbolAddress((void**)&dK, g_K);
    cudaGetSymbolAddress((void**)&dV, g_V);
    cudaGetSymbolAddress((void**)&dS, g_S);

    static bool attr_done = false;
    if (!attr_done) {
        cudaFuncSetAttribute(mma_proj3_k,
                             cudaFuncAttributeMaxDynamicSharedMemorySize, GEMM_SMEM_BYTES);
        cudaFuncSetAttribute(mma_gemm_k<false, false, 3>,
                             cudaFuncAttributeMaxDynamicSharedMemorySize, GEMM_SMEM_BYTES);
        cudaFuncSetAttribute(mma_gemm_k<true, false, 2>,
                             cudaFuncAttributeMaxDynamicSharedMemorySize, GEMM_SMEM_BYTES);
        attr_done = true;
    }

    const long long sQK = (long long)SEQ * DMODEL;
    const long long sS  = (long long)SEQ * SEQ;
    dim3 thr(256);

    // 1) Projections (fused, grid.z picks q/k/v; Q,K x3, V x2)
    dim3 gProj(DMODEL / 128, (BATCH * SEQ) / 128, 3);
    mma_proj3_k<<<gProj, thr, GEMM_SMEM_BYTES>>>(
        query, key_, value, Wq, bq, Wk, bk, Wv, bv, dQ, dK, dV);

    // 2) Scores: S = 8 * Q @ K^T — tf32x3 (precision-critical path)
    dim3 gScore(SEQ / 128, SEQ / 128, BATCH);
    mma_gemm_k<false, false, 3><<<gScore, thr, GEMM_SMEM_BYTES>>>(
        dQ, dK, nullptr, dS, DMODEL, DMODEL, DMODEL, SEQ, 8.0f, sQK, sQK, sS);

    // 3) Softmax + threefry dropout (in place on S)
    dim3 gSm(SEQ, BATCH, 1);
    softmax_dropout_k<<<gSm, thr>>>(dS);

    // 4) Output: O = P @ V — tf32x2 (P split exactly, V rounded rna)
    dim3 gOut(DMODEL / 128, SEQ / 128, BATCH);
    mma_gemm_k<true, false, 2><<<gOut, thr, GEMM_SMEM_BYTES>>>(
        dS, dV, nullptr, out, SEQ, SEQ, DMODEL, DMODEL, 1.0f, sS, sQK, sQK);
}

// round 9
// speedup vs baseline: 1.1370x; 1.0014x over previous
#include <cuda_runtime.h>
#include <cstdint>

// ---------------------------------------------------------------------------
// Problem constants
// ---------------------------------------------------------------------------
#define BATCH  4
#define SEQ    2048
#define DMODEL 1024

// Scratch (device globals: allocation-free)
__device__ float g_Q[(size_t)BATCH * SEQ * DMODEL];
__device__ float g_K[(size_t)BATCH * SEQ * DMODEL];
__device__ float g_V[(size_t)BATCH * SEQ * DMODEL];
__device__ float g_S[(size_t)BATCH * SEQ * SEQ];

// ---------------------------------------------------------------------------
// Helpers
// ---------------------------------------------------------------------------
__device__ __forceinline__ uint32_t smem_u32(const void* p) {
    uint32_t a;
    asm("{ .reg .u64 t; cvta.to.shared.u64 t, %1; cvt.u32.u64 %0, t; }"
        : "=r"(a) : "l"(p));
    return a;
}

#define CP_ASYNC16(saddr, gptr) \
    asm volatile("cp.async.cg.shared.global [%0], [%1], 16;" \
        :: "r"(saddr), "l"(gptr) : "memory")
#define CP_COMMIT() asm volatile("cp.async.commit_group;" ::: "memory")
#define CP_WAIT0()  asm volatile("cp.async.wait_group 0;" ::: "memory")
#define CP_WAIT1()  asm volatile("cp.async.wait_group 1;" ::: "memory")

// tf32x3 split WITHOUT cvt: hi = top-10-mantissa truncation (valid tf32);
// lo passed as raw fp32 bits — the HMMA tf32 datapath truncates to the tf32
// bit subset in hardware (error ~2^-21 |x|, same order as the scheme's
// intrinsic residuals).
__device__ __forceinline__ void split3(float x, uint32_t& hi, uint32_t& lo) {
    const uint32_t h = __float_as_uint(x) & 0xffffe000u;
    hi = h;
    lo = __float_as_uint(x - __uint_as_float(h));
}

// Proper rna rounding (x2-scheme B operand: rounding quality is first-order)
__device__ __forceinline__ uint32_t to_tf32(float x) {
    uint32_t t;
    asm("cvt.rna.tf32.f32 %0, %1;" : "=r"(t) : "f"(x));
    return t;
}

// D += A(16x8 tf32) * B(8x8 tf32), fp32 accumulate
__device__ __forceinline__ void mma8(float* d, const uint32_t* a, const uint32_t* b) {
    asm volatile(
        "mma.sync.aligned.m16n8k8.row.col.f32.tf32.tf32.f32 "
        "{%0,%1,%2,%3}, {%4,%5,%6,%7}, {%8,%9}, {%0,%1,%2,%3};"
        : "+f"(d[0]), "+f"(d[1]), "+f"(d[2]), "+f"(d[3])
        : "r"(a[0]), "r"(a[1]), "r"(a[2]), "r"(a[3]), "r"(b[0]), "r"(b[1]));
}

// ---------------------------------------------------------------------------
// tf32 emulated GEMM body: C[m,n] = alpha * sum_k A[m,k]*Bmat[k,n] (+ bias[n])
//   TRANSB_LOAD=false: Bmat[k,n] = B[n*ldb + k]  (B K-major [N,K], e.g. K^T)
//   TRANSB_LOAD=true : Bmat[k,n] = B[k*ldb + n]  (B MN-major [K,N], e.g. W, V)
//   SCHEME=3: D += Ah*Bh + Ah*Bl + Al*Bh   (fp32-accurate)
//   SCHEME=2: D += Ah*Bt + Al*Bt           (A exact, B rounded rna ~2^-12)
// BM=BN=128, KC=32, 256 threads (8 warps, each 64x32), cp.async 2-stage.
// MMA issue order: product-type outer, nt inner -> accumulator reuse
// distance = 4 independent MMAs (hides HMMA RAW latency).
// ---------------------------------------------------------------------------
#define A_TILE_F 4608            // 128 * 36 floats
#define B_TILE_F 4608            // >= max(128*36 direct, 32*136 trans)
#define STAGE_F  (A_TILE_F + B_TILE_F)
#define GEMM_SMEM_BYTES (2 * STAGE_F * 4)

template <bool TRANSB_LOAD, bool HASBIAS, int SCHEME>
__device__ __forceinline__
void gemm_body(const float* __restrict__ A, const float* __restrict__ B,
               const float* __restrict__ bias, float* __restrict__ C,
               int K, int lda, int ldb, int ldc, float alpha)
{
    extern __shared__ float smem[];

    const int tid  = threadIdx.x;
    const int wid  = tid >> 5;
    const int lane = tid & 31;
    const int tg   = lane >> 2;      // 0..7
    const int tk   = lane & 3;       // 0..3
    const int row0 = blockIdx.y * 128;
    const int col0 = blockIdx.x * 128;
    const int wm   = (wid >> 2) * 64;   // warp m-offset in tile
    const int wn   = (wid & 3) * 32;    // warp n-offset in tile

    float acc[4][4][4];
#pragma unroll
    for (int mt = 0; mt < 4; mt++)
#pragma unroll
        for (int nt = 0; nt < 4; nt++)
#pragma unroll
            for (int e = 0; e < 4; e++) acc[mt][nt][e] = 0.0f;

    // ---- stage fill via cp.async ----
    auto fill = [&](int st, int k0) {
        float* base = smem + st * STAGE_F;
        const uint32_t sAa = smem_u32(base);
        const uint32_t sBa = smem_u32(base + A_TILE_F);
        // A tile: [128 m][32 k], k-contiguous global
#pragma unroll
        for (int j = 0; j < 4; j++) {
            const int idx = tid + j * 256;
            const int r  = idx >> 3;
            const int c4 = (idx & 7) << 2;
            CP_ASYNC16(sAa + (uint32_t)(r * 36 + c4) * 4u,
                       A + (size_t)(row0 + r) * lda + k0 + c4);
        }
        if (TRANSB_LOAD) {
            // B global [K,N] n-contiguous -> smem [32 k][128 n], ld=136
#pragma unroll
            for (int j = 0; j < 4; j++) {
                const int idx = tid + j * 256;
                const int kk = idx >> 5;
                const int n4 = (idx & 31) << 2;
                CP_ASYNC16(sBa + (uint32_t)(kk * 136 + n4) * 4u,
                           B + (size_t)(k0 + kk) * ldb + col0 + n4);
            }
        } else {
            // B global [N,K] k-contiguous -> smem [128 n][32 k], ld=36
#pragma unroll
            for (int j = 0; j < 4; j++) {
                const int idx = tid + j * 256;
                const int r  = idx >> 3;
                const int c4 = (idx & 7) << 2;
                CP_ASYNC16(sBa + (uint32_t)(r * 36 + c4) * 4u,
                           B + (size_t)(col0 + r) * ldb + k0 + c4);
            }
        }
        CP_COMMIT();
    };

    // ---- compute one staged chunk (4 k8-steps) ----
    auto compute = [&](int st) {
        const float* sA = smem + st * STAGE_F;
        const float* sB = sA + A_TILE_F;
#pragma unroll
        for (int s = 0; s < 4; s++) {
            // B fragments for all 4 nt
            uint32_t bh[4][2], bl[4][2];
#pragma unroll
            for (int nt = 0; nt < 4; nt++) {
                const int n0 = wn + nt * 8;
                float b0, b1;
                if (TRANSB_LOAD) {
                    b0 = sB[(s * 8 + tk)     * 136 + n0 + tg];
                    b1 = sB[(s * 8 + tk + 4) * 136 + n0 + tg];
                } else {
                    b0 = sB[(n0 + tg) * 36 + s * 8 + tk];
                    b1 = sB[(n0 + tg) * 36 + s * 8 + tk + 4];
                }
                if (SCHEME == 3) {
                    split3(b0, bh[nt][0], bl[nt][0]);
                    split3(b1, bh[nt][1], bl[nt][1]);
                } else {
                    bh[nt][0] = to_tf32(b0);
                    bh[nt][1] = to_tf32(b1);
                }
            }
            // A fragments per mt; MMAs grouped by product type so that
            // consecutive MMAs target DIFFERENT accumulators (reuse dist 4).
#pragma unroll
            for (int mt = 0; mt < 4; mt++) {
                const int m0 = wm + mt * 16;
                uint32_t ah[4], al[4];
                split3(sA[(m0 + tg)     * 36 + s * 8 + tk],     ah[0], al[0]);
                split3(sA[(m0 + tg + 8) * 36 + s * 8 + tk],     ah[1], al[1]);
                split3(sA[(m0 + tg)     * 36 + s * 8 + tk + 4], ah[2], al[2]);
                split3(sA[(m0 + tg + 8) * 36 + s * 8 + tk + 4], ah[3], al[3]);
#pragma unroll
                for (int nt = 0; nt < 4; nt++) mma8(acc[mt][nt], ah, bh[nt]);
                if (SCHEME == 3) {
#pragma unroll
                    for (int nt = 0; nt < 4; nt++) mma8(acc[mt][nt], ah, bl[nt]);
                }
#pragma unroll
                for (int nt = 0; nt < 4; nt++) mma8(acc[mt][nt], al, bh[nt]);
            }
        }
    };

    const int nchunk = K >> 5;   // K/32
    fill(0, 0);
    for (int i = 0; i < nchunk; i++) {
        if (i + 1 < nchunk) { fill((i + 1) & 1, (i + 1) << 5); CP_WAIT1(); }
        else                { CP_WAIT0(); }
        __syncthreads();
        compute(i & 1);
        __syncthreads();
    }

    // ---- epilogue ----
#pragma unroll
    for (int mt = 0; mt < 4; mt++) {
        const int r = row0 + wm + mt * 16 + tg;
#pragma unroll
        for (int nt = 0; nt < 4; nt++) {
            const int col = col0 + wn + nt * 8 + tk * 2;
            float2 v0, v1;
            v0.x = acc[mt][nt][0] * alpha;
            v0.y = acc[mt][nt][1] * alpha;
            v1.x = acc[mt][nt][2] * alpha;
            v1.y = acc[mt][nt][3] * alpha;
            if (HASBIAS) {
                const float b0 = bias[col], b1 = bias[col + 1];
                v0.x += b0; v0.y += b1;
                v1.x += b0; v1.y += b1;
            }
            *(float2*)(C + (size_t)r * ldc + col)       = v0;
            *(float2*)(C + (size_t)(r + 8) * ldc + col) = v1;
        }
    }
}

// Generic batched GEMM kernel (2 CTAs/SM)
template <bool TRANSB_LOAD, bool HASBIAS, int SCHEME>
__global__ __launch_bounds__(256, 2)
void mma_gemm_k(const float* __restrict__ Ag, const float* __restrict__ Bg,
                const float* __restrict__ bias, float* __restrict__ Cg,
                int K, int lda, int ldb, int ldc, float alpha,
                long long sA, long long sB, long long sC)
{
    const int z = blockIdx.z;
    gemm_body<TRANSB_LOAD, HASBIAS, SCHEME>(Ag + (long long)z * sA,
                                            Bg + (long long)z * sB,
                                            bias, Cg + (long long)z * sC,
                                            K, lda, ldb, ldc, alpha);
}

// Fused Q/K/V projection: blockIdx.z picks which projection.
// Q,K at x3 (feed the precision-critical score path); V at x2.
__global__ __launch_bounds__(256, 2)
void mma_proj3_k(const float* __restrict__ q, const float* __restrict__ k,
                 const float* __restrict__ v,
                 const float* __restrict__ Wq, const float* __restrict__ bq,
                 const float* __restrict__ Wk, const float* __restrict__ bk,
                 const float* __restrict__ Wv, const float* __restrict__ bv,
                 float* __restrict__ Q, float* __restrict__ K, float* __restrict__ V)
{
    if (blockIdx.z == 0)
        gemm_body<true, true, 3>(q, Wq, bq, Q, DMODEL, DMODEL, DMODEL, DMODEL, 1.0f);
    else if (blockIdx.z == 1)
        gemm_body<true, true, 3>(k, Wk, bk, K, DMODEL, DMODEL, DMODEL, DMODEL, 1.0f);
    else
        gemm_body<true, true, 2>(v, Wv, bv, V, DMODEL, DMODEL, DMODEL, DMODEL, 1.0f);
}

// ---------------------------------------------------------------------------
// JAX threefry2x32, key (0,42), partitionable scheme:
//   bits[i] = y0 ^ y1 of threefry2x32(key, (0, i)); keep <=> MSB==0
// ---------------------------------------------------------------------------
__device__ __forceinline__ uint32_t threefry_mask_word(uint32_t idx)
{
    const uint32_t ks0 = 0u;
    const uint32_t ks1 = 42u;
    const uint32_t ks2 = 42u ^ 0x1BD11BDAu;
    uint32_t x0 = ks0;
    uint32_t x1 = idx + ks1;
#define TFR(r) { x0 += x1; x1 = __funnelshift_l(x1, x1, (r)); x1 ^= x0; }
    TFR(13) TFR(15) TFR(26) TFR(6)
    x0 += ks1; x1 += ks2 + 1u;
    TFR(17) TFR(29) TFR(16) TFR(24)
    x0 += ks2; x1 += ks0 + 2u;
    TFR(13) TFR(15) TFR(26) TFR(6)
    x0 += ks0; x1 += ks1 + 3u;
    TFR(17) TFR(29) TFR(16) TFR(24)
    x0 += ks1; x1 += ks2 + 4u;
    TFR(13) TFR(15) TFR(26) TFR(6)
    x0 += ks2; x1 += ks0 + 5u;
#undef TFR
    return x0 ^ x1;
}

// ---------------------------------------------------------------------------
// Softmax + dropout, one block per (b,q) row of S. kept value scaled by 2.
// ---------------------------------------------------------------------------
__global__ __launch_bounds__(256, 4)
void softmax_dropout_k(float* __restrict__ S)
{
    const int q   = blockIdx.x;
    const int b   = blockIdx.y;
    const int tid = threadIdx.x;
    float* __restrict__ row = S + ((size_t)b * SEQ + q) * SEQ;

    float a[8];
#pragma unroll
    for (int j = 0; j < 8; j++) a[j] = row[tid + j * 256];

    float m = a[0];
#pragma unroll
    for (int j = 1; j < 8; j++) m = fmaxf(m, a[j]);
#pragma unroll
    for (int s = 16; s > 0; s >>= 1)
        m = fmaxf(m, __shfl_xor_sync(0xffffffffu, m, s));
    __shared__ float red[8];
    const int wid = tid >> 5, lane = tid & 31;
    if (lane == 0) red[wid] = m;
    __syncthreads();
    m = red[0];
#pragma unroll
    for (int w = 1; w < 8; w++) m = fmaxf(m, red[w]);
    __syncthreads();

    float s0 = 0.0f;
#pragma unroll
    for (int j = 0; j < 8; j++) {
        a[j] = __expf(a[j] - m);
        s0 += a[j];
    }
#pragma unroll
    for (int s = 16; s > 0; s >>= 1)
        s0 += __shfl_xor_sync(0xffffffffu, s0, s);
    if (lane == 0) red[wid] = s0;
    __syncthreads();
    s0 = 0.0f;
#pragma unroll
    for (int w = 0; w < 8; w++) s0 += red[w];

    const float inv = 2.0f / s0;

    const uint32_t base = ((uint32_t)(b * SEQ + q)) * (uint32_t)SEQ;
#pragma unroll
    for (int j = 0; j < 8; j++) {
        const uint32_t k = (uint32_t)tid + (uint32_t)j * 256u;
        const uint32_t w = threefry_mask_word(base + k);
        row[k] = (w >> 31) ? 0.0f : a[j] * inv;
    }
}

// ---------------------------------------------------------------------------
// Launcher
// ---------------------------------------------------------------------------
extern "C" void kernel_launch(void* const* d_in, const int* in_sizes, int n_in,
                              void* d_out, int out_size)
{
    (void)in_sizes; (void)n_in; (void)out_size;
    const float* query = (const float*)d_in[0];
    const float* key_  = (const float*)d_in[1];
    const float* value = (const float*)d_in[2];
    const float* Wq    = (const float*)d_in[3];
    const float* bq    = (const float*)d_in[4];
    const float* Wk    = (const float*)d_in[5];
    const float* bk    = (const float*)d_in[6];
    const float* Wv    = (const float*)d_in[7];
    const float* bv    = (const float*)d_in[8];
    float* out = (float*)d_out;

    float *dQ, *dK, *dV, *dS;
    cudaGetSymbolAddress((void**)&dQ, g_Q);
    cudaGetSymbolAddress((void**)&dK, g_K);
    cudaGetSymbolAddress((void**)&dV, g_V);
    cudaGetSymbolAddress((void**)&dS, g_S);

    static bool attr_done = false;
    if (!attr_done) {
        cudaFuncSetAttribute(mma_proj3_k,
                             cudaFuncAttributeMaxDynamicSharedMemorySize, GEMM_SMEM_BYTES);
        cudaFuncSetAttribute(mma_gemm_k<false, false, 3>,
                             cudaFuncAttributeMaxDynamicSharedMemorySize, GEMM_SMEM_BYTES);
        cudaFuncSetAttribute(mma_gemm_k<true, false, 2>,
                             cudaFuncAttributeMaxDynamicSharedMemorySize, GEMM_SMEM_BYTES);
        attr_done = true;
    }

    const long long sQK = (long long)SEQ * DMODEL;
    const long long sS  = (long long)SEQ * SEQ;
    dim3 thr(256);

    // 1) Projections (fused, grid.z picks q/k/v; Q,K x3, V x2)
    dim3 gProj(DMODEL / 128, (BATCH * SEQ) / 128, 3);
    mma_proj3_k<<<gProj, thr, GEMM_SMEM_BYTES>>>(
        query, key_, value, Wq, bq, Wk, bk, Wv, bv, dQ, dK, dV);

    // 2) Scores: S = 8 * Q @ K^T — tf32x3 (precision-critical path)
    dim3 gScore(SEQ / 128, SEQ / 128, BATCH);
    mma_gemm_k<false, false, 3><<<gScore, thr, GEMM_SMEM_BYTES>>>(
        dQ, dK, nullptr, dS, DMODEL, DMODEL, DMODEL, SEQ, 8.0f, sQK, sQK, sS);

    // 3) Softmax + threefry dropout (in place on S)
    dim3 gSm(SEQ, BATCH, 1);
    softmax_dropout_k<<<gSm, thr>>>(dS);

    // 4) Output: O = P @ V — tf32x2 (P split exactly, V rounded rna)
    dim3 gOut(DMODEL / 128, SEQ / 128, BATCH);
    mma_gemm_k<true, false, 2><<<gOut, thr, GEMM_SMEM_BYTES>>>(
        dS, dV, nullptr, out, SEQ, SEQ, DMODEL, DMODEL, 1.0f, sS, sQK, sQK);
}

// round 10
// speedup vs baseline: 1.2245x; 1.0770x over previous
#include <cuda_runtime.h>
#include <cstdint>

// ---------------------------------------------------------------------------
// Problem constants
// ---------------------------------------------------------------------------
#define BATCH  4
#define SEQ    2048
#define DMODEL 1024

// Scratch (device globals: allocation-free)
__device__ float g_Q[(size_t)BATCH * SEQ * DMODEL];
__device__ float g_K[(size_t)BATCH * SEQ * DMODEL];
__device__ float g_V[(size_t)BATCH * SEQ * DMODEL];
__device__ float g_S[(size_t)BATCH * SEQ * SEQ];

// ---------------------------------------------------------------------------
// Helpers
// ---------------------------------------------------------------------------
__device__ __forceinline__ uint32_t smem_u32(const void* p) {
    uint32_t a;
    asm("{ .reg .u64 t; cvta.to.shared.u64 t, %1; cvt.u32.u64 %0, t; }"
        : "=r"(a) : "l"(p));
    return a;
}

#define CP_ASYNC16(saddr, gptr) \
    asm volatile("cp.async.cg.shared.global [%0], [%1], 16;" \
        :: "r"(saddr), "l"(gptr) : "memory")
#define CP_COMMIT() asm volatile("cp.async.commit_group;" ::: "memory")
#define CP_WAIT0()  asm volatile("cp.async.wait_group 0;" ::: "memory")
#define CP_WAIT1()  asm volatile("cp.async.wait_group 1;" ::: "memory")

// tf32x3 split WITHOUT cvt: hi = top-10-mantissa truncation (valid tf32);
// lo passed as raw fp32 bits — the HMMA tf32 datapath truncates to the tf32
// bit subset in hardware (error ~2^-21 |x|, same order as the scheme's
// intrinsic residuals).
__device__ __forceinline__ void split3(float x, uint32_t& hi, uint32_t& lo) {
    const uint32_t h = __float_as_uint(x) & 0xffffe000u;
    hi = h;
    lo = __float_as_uint(x - __uint_as_float(h));
}

// Proper rna rounding (x1/x2-scheme operands: rounding quality first-order)
__device__ __forceinline__ uint32_t to_tf32(float x) {
    uint32_t t;
    asm("cvt.rna.tf32.f32 %0, %1;" : "=r"(t) : "f"(x));
    return t;
}

// D += A(16x8 tf32) * B(8x8 tf32), fp32 accumulate
__device__ __forceinline__ void mma8(float* d, const uint32_t* a, const uint32_t* b) {
    asm volatile(
        "mma.sync.aligned.m16n8k8.row.col.f32.tf32.tf32.f32 "
        "{%0,%1,%2,%3}, {%4,%5,%6,%7}, {%8,%9}, {%0,%1,%2,%3};"
        : "+f"(d[0]), "+f"(d[1]), "+f"(d[2]), "+f"(d[3])
        : "r"(a[0]), "r"(a[1]), "r"(a[2]), "r"(a[3]), "r"(b[0]), "r"(b[1]));
}

// ---------------------------------------------------------------------------
// tf32 emulated GEMM body: C[m,n] = alpha * sum_k A[m,k]*Bmat[k,n] (+ bias[n])
//   TRANSB_LOAD=false: Bmat[k,n] = B[n*ldb + k]  (B K-major [N,K], e.g. K^T)
//   TRANSB_LOAD=true : Bmat[k,n] = B[k*ldb + n]  (B MN-major [K,N], e.g. W, V)
//   SCHEME=3: D += Ah*Bh + Ah*Bl + Al*Bh   (fp32-accurate)
//   SCHEME=2: D += Ah*Bt + Al*Bt           (A exact, B rounded rna)
//   SCHEME=1: D += At*Bt                   (both rounded rna)
// BM=BN=128, KC=32, 256 threads (8 warps, each 64x32).
// 3-stage cp.async pipeline, ONE __syncthreads per chunk.
// ---------------------------------------------------------------------------
#define A_TILE_F 4608            // 128 * 36 floats
#define B_TILE_F 4608            // >= max(128*36 direct, 32*136 trans)
#define STAGE_F  (A_TILE_F + B_TILE_F)
#define STAGES   3
#define GEMM_SMEM_BYTES (STAGES * STAGE_F * 4)   // 110592

template <bool TRANSB_LOAD, bool HASBIAS, int SCHEME>
__device__ __forceinline__
void gemm_body(const float* __restrict__ A, const float* __restrict__ B,
               const float* __restrict__ bias, float* __restrict__ C,
               int K, int lda, int ldb, int ldc, float alpha)
{
    extern __shared__ float smem[];

    const int tid  = threadIdx.x;
    const int wid  = tid >> 5;
    const int lane = tid & 31;
    const int tg   = lane >> 2;      // 0..7
    const int tk   = lane & 3;       // 0..3
    const int row0 = blockIdx.y * 128;
    const int col0 = blockIdx.x * 128;
    const int wm   = (wid >> 2) * 64;   // warp m-offset in tile
    const int wn   = (wid & 3) * 32;    // warp n-offset in tile

    float acc[4][4][4];
#pragma unroll
    for (int mt = 0; mt < 4; mt++)
#pragma unroll
        for (int nt = 0; nt < 4; nt++)
#pragma unroll
            for (int e = 0; e < 4; e++) acc[mt][nt][e] = 0.0f;

    // ---- stage fill via cp.async ----
    auto fill = [&](int st, int k0) {
        float* base = smem + st * STAGE_F;
        const uint32_t sAa = smem_u32(base);
        const uint32_t sBa = smem_u32(base + A_TILE_F);
        // A tile: [128 m][32 k], k-contiguous global
#pragma unroll
        for (int j = 0; j < 4; j++) {
            const int idx = tid + j * 256;
            const int r  = idx >> 3;
            const int c4 = (idx & 7) << 2;
            CP_ASYNC16(sAa + (uint32_t)(r * 36 + c4) * 4u,
                       A + (size_t)(row0 + r) * lda + k0 + c4);
        }
        if (TRANSB_LOAD) {
            // B global [K,N] n-contiguous -> smem [32 k][128 n], ld=136
#pragma unroll
            for (int j = 0; j < 4; j++) {
                const int idx = tid + j * 256;
                const int kk = idx >> 5;
                const int n4 = (idx & 31) << 2;
                CP_ASYNC16(sBa + (uint32_t)(kk * 136 + n4) * 4u,
                           B + (size_t)(k0 + kk) * ldb + col0 + n4);
            }
        } else {
            // B global [N,K] k-contiguous -> smem [128 n][32 k], ld=36
#pragma unroll
            for (int j = 0; j < 4; j++) {
                const int idx = tid + j * 256;
                const int r  = idx >> 3;
                const int c4 = (idx & 7) << 2;
                CP_ASYNC16(sBa + (uint32_t)(r * 36 + c4) * 4u,
                           B + (size_t)(col0 + r) * ldb + k0 + c4);
            }
        }
        CP_COMMIT();
    };

    // ---- compute one staged chunk (4 k8-steps) ----
    auto compute = [&](int st) {
        const float* sA = smem + st * STAGE_F;
        const float* sB = sA + A_TILE_F;
#pragma unroll
        for (int s = 0; s < 4; s++) {
            // B fragments for all 4 nt
            uint32_t bh[4][2], bl[4][2];
#pragma unroll
            for (int nt = 0; nt < 4; nt++) {
                const int n0 = wn + nt * 8;
                float b0, b1;
                if (TRANSB_LOAD) {
                    b0 = sB[(s * 8 + tk)     * 136 + n0 + tg];
                    b1 = sB[(s * 8 + tk + 4) * 136 + n0 + tg];
                } else {
                    b0 = sB[(n0 + tg) * 36 + s * 8 + tk];
                    b1 = sB[(n0 + tg) * 36 + s * 8 + tk + 4];
                }
                if (SCHEME == 3) {
                    split3(b0, bh[nt][0], bl[nt][0]);
                    split3(b1, bh[nt][1], bl[nt][1]);
                } else {
                    bh[nt][0] = to_tf32(b0);
                    bh[nt][1] = to_tf32(b1);
                }
            }
            // A fragments per mt
#pragma unroll
            for (int mt = 0; mt < 4; mt++) {
                const int m0 = wm + mt * 16;
                const float a0 = sA[(m0 + tg)     * 36 + s * 8 + tk];
                const float a1 = sA[(m0 + tg + 8) * 36 + s * 8 + tk];
                const float a2 = sA[(m0 + tg)     * 36 + s * 8 + tk + 4];
                const float a3 = sA[(m0 + tg + 8) * 36 + s * 8 + tk + 4];
                if (SCHEME == 1) {
                    uint32_t at[4];
                    at[0] = to_tf32(a0);
                    at[1] = to_tf32(a1);
                    at[2] = to_tf32(a2);
                    at[3] = to_tf32(a3);
#pragma unroll
                    for (int nt = 0; nt < 4; nt++) mma8(acc[mt][nt], at, bh[nt]);
                } else {
                    uint32_t ah[4], al[4];
                    split3(a0, ah[0], al[0]);
                    split3(a1, ah[1], al[1]);
                    split3(a2, ah[2], al[2]);
                    split3(a3, ah[3], al[3]);
#pragma unroll
                    for (int nt = 0; nt < 4; nt++) mma8(acc[mt][nt], ah, bh[nt]);
                    if (SCHEME == 3) {
#pragma unroll
                        for (int nt = 0; nt < 4; nt++) mma8(acc[mt][nt], ah, bl[nt]);
                    }
#pragma unroll
                    for (int nt = 0; nt < 4; nt++) mma8(acc[mt][nt], al, bh[nt]);
                }
            }
        }
    };

    // ---- 3-stage mainloop, one barrier per chunk ----
    // Invariants at top of iter i: groups for chunks <= i-1 retired is NOT
    // yet guaranteed; CP_WAIT1 leaves at most 1 pending group (chunk i+1),
    // so chunk i's data is in smem. The barrier then (a) makes it visible
    // block-wide, (b) separates all warps' reads of stage (i+2)%3 (done in
    // compute(i-1)) from this iteration's fill of that stage.
    const int nchunk = K >> 5;   // K/32, >= 2 always here
    fill(0, 0);
    fill(1, 32);
    for (int i = 0; i < nchunk; i++) {
        if (i + 1 < nchunk) { CP_WAIT1(); }
        else                { CP_WAIT0(); }
        __syncthreads();
        if (i + 2 < nchunk) fill((i + 2) % STAGES, (i + 2) << 5);
        compute(i % STAGES);
    }

    // ---- epilogue ----
#pragma unroll
    for (int mt = 0; mt < 4; mt++) {
        const int r = row0 + wm + mt * 16 + tg;
#pragma unroll
        for (int nt = 0; nt < 4; nt++) {
            const int col = col0 + wn + nt * 8 + tk * 2;
            float2 v0, v1;
            v0.x = acc[mt][nt][0] * alpha;
            v0.y = acc[mt][nt][1] * alpha;
            v1.x = acc[mt][nt][2] * alpha;
            v1.y = acc[mt][nt][3] * alpha;
            if (HASBIAS) {
                const float b0 = bias[col], b1 = bias[col + 1];
                v0.x += b0; v0.y += b1;
                v1.x += b0; v1.y += b1;
            }
            *(float2*)(C + (size_t)r * ldc + col)       = v0;
            *(float2*)(C + (size_t)(r + 8) * ldc + col) = v1;
        }
    }
}

// Generic batched GEMM kernel (2 CTAs/SM)
template <bool TRANSB_LOAD, bool HASBIAS, int SCHEME>
__global__ __launch_bounds__(256, 2)
void mma_gemm_k(const float* __restrict__ Ag, const float* __restrict__ Bg,
                const float* __restrict__ bias, float* __restrict__ Cg,
                int K, int lda, int ldb, int ldc, float alpha,
                long long sA, long long sB, long long sC)
{
    const int z = blockIdx.z;
    gemm_body<TRANSB_LOAD, HASBIAS, SCHEME>(Ag + (long long)z * sA,
                                            Bg + (long long)z * sB,
                                            bias, Cg + (long long)z * sC,
                                            K, lda, ldb, ldc, alpha);
}

// Fused Q/K/V projection: blockIdx.z picks which projection.
// Q,K at x3 (feed the precision-critical score path); V at x2.
__global__ __launch_bounds__(256, 2)
void mma_proj3_k(const float* __restrict__ q, const float* __restrict__ k,
                 const float* __restrict__ v,
                 const float* __restrict__ Wq, const float* __restrict__ bq,
                 const float* __restrict__ Wk, const float* __restrict__ bk,
                 const float* __restrict__ Wv, const float* __restrict__ bv,
                 float* __restrict__ Q, float* __restrict__ K, float* __restrict__ V)
{
    if (blockIdx.z == 0)
        gemm_body<true, true, 3>(q, Wq, bq, Q, DMODEL, DMODEL, DMODEL, DMODEL, 1.0f);
    else if (blockIdx.z == 1)
        gemm_body<true, true, 3>(k, Wk, bk, K, DMODEL, DMODEL, DMODEL, DMODEL, 1.0f);
    else
        gemm_body<true, true, 2>(v, Wv, bv, V, DMODEL, DMODEL, DMODEL, DMODEL, 1.0f);
}

// ---------------------------------------------------------------------------
// JAX threefry2x32, key (0,42), partitionable scheme:
//   bits[i] = y0 ^ y1 of threefry2x32(key, (0, i)); keep <=> MSB==0
// ---------------------------------------------------------------------------
__device__ __forceinline__ uint32_t threefry_mask_word(uint32_t idx)
{
    const uint32_t ks0 = 0u;
    const uint32_t ks1 = 42u;
    const uint32_t ks2 = 42u ^ 0x1BD11BDAu;
    uint32_t x0 = ks0;
    uint32_t x1 = idx + ks1;
#define TFR(r) { x0 += x1; x1 = __funnelshift_l(x1, x1, (r)); x1 ^= x0; }
    TFR(13) TFR(15) TFR(26) TFR(6)
    x0 += ks1; x1 += ks2 + 1u;
    TFR(17) TFR(29) TFR(16) TFR(24)
    x0 += ks2; x1 += ks0 + 2u;
    TFR(13) TFR(15) TFR(26) TFR(6)
    x0 += ks0; x1 += ks1 + 3u;
    TFR(17) TFR(29) TFR(16) TFR(24)
    x0 += ks1; x1 += ks2 + 4u;
    TFR(13) TFR(15) TFR(26) TFR(6)
    x0 += ks2; x1 += ks0 + 5u;
#undef TFR
    return x0 ^ x1;
}

// ---------------------------------------------------------------------------
// Softmax + dropout, one block per (b,q) row of S. kept value scaled by 2.
// ---------------------------------------------------------------------------
__global__ __launch_bounds__(256, 4)
void softmax_dropout_k(float* __restrict__ S)
{
    const int q   = blockIdx.x;
    const int b   = blockIdx.y;
    const int tid = threadIdx.x;
    float* __restrict__ row = S + ((size_t)b * SEQ + q) * SEQ;

    float a[8];
#pragma unroll
    for (int j = 0; j < 8; j++) a[j] = row[tid + j * 256];

    float m = a[0];
#pragma unroll
    for (int j = 1; j < 8; j++) m = fmaxf(m, a[j]);
#pragma unroll
    for (int s = 16; s > 0; s >>= 1)
        m = fmaxf(m, __shfl_xor_sync(0xffffffffu, m, s));
    __shared__ float red[8];
    const int wid = tid >> 5, lane = tid & 31;
    if (lane == 0) red[wid] = m;
    __syncthreads();
    m = red[0];
#pragma unroll
    for (int w = 1; w < 8; w++) m = fmaxf(m, red[w]);
    __syncthreads();

    float s0 = 0.0f;
#pragma unroll
    for (int j = 0; j < 8; j++) {
        a[j] = __expf(a[j] - m);
        s0 += a[j];
    }
#pragma unroll
    for (int s = 16; s > 0; s >>= 1)
        s0 += __shfl_xor_sync(0xffffffffu, s0, s);
    if (lane == 0) red[wid] = s0;
    __syncthreads();
    s0 = 0.0f;
#pragma unroll
    for (int w = 0; w < 8; w++) s0 += red[w];

    const float inv = 2.0f / s0;

    const uint32_t base = ((uint32_t)(b * SEQ + q)) * (uint32_t)SEQ;
#pragma unroll
    for (int j = 0; j < 8; j++) {
        const uint32_t k = (uint32_t)tid + (uint32_t)j * 256u;
        const uint32_t w = threefry_mask_word(base + k);
        row[k] = (w >> 31) ? 0.0f : a[j] * inv;
    }
}

// ---------------------------------------------------------------------------
// Launcher
// ---------------------------------------------------------------------------
extern "C" void kernel_launch(void* const* d_in, const int* in_sizes, int n_in,
                              void* d_out, int out_size)
{
    (void)in_sizes; (void)n_in; (void)out_size;
    const float* query = (const float*)d_in[0];
    const float* key_  = (const float*)d_in[1];
    const float* value = (const float*)d_in[2];
    const float* Wq    = (const float*)d_in[3];
    const float* bq    = (const float*)d_in[4];
    const float* Wk    = (const float*)d_in[5];
    const float* bk    = (const float*)d_in[6];
    const float* Wv    = (const float*)d_in[7];
    const float* bv    = (const float*)d_in[8];
    float* out = (float*)d_out;

    float *dQ, *dK, *dV, *dS;
    cudaGetSymbolAddress((void**)&dQ, g_Q);
    cudaGetSymbolAddress((void**)&dK, g_K);
    cudaGetSymbolAddress((void**)&dV, g_V);
    cudaGetSymbolAddress((void**)&dS, g_S);

    static bool attr_done = false;
    if (!attr_done) {
        cudaFuncSetAttribute(mma_proj3_k,
                             cudaFuncAttributeMaxDynamicSharedMemorySize, GEMM_SMEM_BYTES);
        cudaFuncSetAttribute(mma_gemm_k<false, false, 3>,
                             cudaFuncAttributeMaxDynamicSharedMemorySize, GEMM_SMEM_BYTES);
        cudaFuncSetAttribute(mma_gemm_k<true, false, 1>,
                             cudaFuncAttributeMaxDynamicSharedMemorySize, GEMM_SMEM_BYTES);
        attr_done = true;
    }

    const long long sQK = (long long)SEQ * DMODEL;
    const long long sS  = (long long)SEQ * SEQ;
    dim3 thr(256);

    // 1) Projections (fused, grid.z picks q/k/v; Q,K x3, V x2)
    dim3 gProj(DMODEL / 128, (BATCH * SEQ) / 128, 3);
    mma_proj3_k<<<gProj, thr, GEMM_SMEM_BYTES>>>(
        query, key_, value, Wq, bq, Wk, bk, Wv, bv, dQ, dK, dV);

    // 2) Scores: S = 8 * Q @ K^T — tf32x3 (precision-critical path)
    dim3 gScore(SEQ / 128, SEQ / 128, BATCH);
    mma_gemm_k<false, false, 3><<<gScore, thr, GEMM_SMEM_BYTES>>>(
        dQ, dK, nullptr, dS, DMODEL, DMODEL, DMODEL, SEQ, 8.0f, sQK, sQK, sS);

    // 3) Softmax + threefry dropout (in place on S)
    dim3 gSm(SEQ, BATCH, 1);
    softmax_dropout_k<<<gSm, thr>>>(dS);

    // 4) Output: O = P @ V — tf32x1 (P and V rounded rna; calibrated ledger
    //    predicts total rel_err ~3.7e-4, within the 1e-3 gate)
    dim3 gOut(DMODEL / 128, SEQ / 128, BATCH);
    mma_gemm_k<true, false, 1><<<gOut, thr, GEMM_SMEM_BYTES>>>(
        dS, dV, nullptr, out, SEQ, SEQ, DMODEL, DMODEL, 1.0f, sS, sQK, sQK);
}

// round 11
// speedup vs baseline: 1.2670x; 1.0347x over previous
#include <cuda_runtime.h>
#include <cstdint>

// ---------------------------------------------------------------------------
// Problem constants
// ---------------------------------------------------------------------------
#define BATCH  4
#define SEQ    2048
#define DMODEL 1024

// Scratch (device globals: allocation-free)
__device__ float g_Q[(size_t)BATCH * SEQ * DMODEL];
__device__ float g_K[(size_t)BATCH * SEQ * DMODEL];
__device__ float g_V[(size_t)BATCH * SEQ * DMODEL];   // pre-rounded tf32 bits
__device__ float g_S[(size_t)BATCH * SEQ * SEQ];      // scores, then tf32 P

// ---------------------------------------------------------------------------
// Helpers
// ---------------------------------------------------------------------------
__device__ __forceinline__ uint32_t smem_u32(const void* p) {
    uint32_t a;
    asm("{ .reg .u64 t; cvta.to.shared.u64 t, %1; cvt.u32.u64 %0, t; }"
        : "=r"(a) : "l"(p));
    return a;
}

#define CP_ASYNC16(saddr, gptr) \
    asm volatile("cp.async.cg.shared.global [%0], [%1], 16;" \
        :: "r"(saddr), "l"(gptr) : "memory")
#define CP_COMMIT() asm volatile("cp.async.commit_group;" ::: "memory")
#define CP_WAIT0()  asm volatile("cp.async.wait_group 0;" ::: "memory")
#define CP_WAIT1()  asm volatile("cp.async.wait_group 1;" ::: "memory")

// tf32x3 split WITHOUT cvt: hi = top-10-mantissa truncation (valid tf32);
// lo passed as raw fp32 bits (HMMA truncates to tf32 subset in HW).
__device__ __forceinline__ void split3(float x, uint32_t& hi, uint32_t& lo) {
    const uint32_t h = __float_as_uint(x) & 0xffffe000u;
    hi = h;
    lo = __float_as_uint(x - __uint_as_float(h));
}

// Proper rna rounding (single-rounding operands: quality is first-order)
__device__ __forceinline__ uint32_t to_tf32(float x) {
    uint32_t t;
    asm("cvt.rna.tf32.f32 %0, %1;" : "=r"(t) : "f"(x));
    return t;
}

// D += A(16x8 tf32) * B(8x8 tf32), fp32 accumulate
__device__ __forceinline__ void mma8(float* d, const uint32_t* a, const uint32_t* b) {
    asm volatile(
        "mma.sync.aligned.m16n8k8.row.col.f32.tf32.tf32.f32 "
        "{%0,%1,%2,%3}, {%4,%5,%6,%7}, {%8,%9}, {%0,%1,%2,%3};"
        : "+f"(d[0]), "+f"(d[1]), "+f"(d[2]), "+f"(d[3])
        : "r"(a[0]), "r"(a[1]), "r"(a[2]), "r"(a[3]), "r"(b[0]), "r"(b[1]));
}

// ---------------------------------------------------------------------------
// tf32 emulated GEMM body.
//   TRANSB_LOAD=false: Bmat[k,n] = B[n*ldb + k]  (B K-major [N,K], e.g. K^T)
//   TRANSB_LOAD=true : Bmat[k,n] = B[k*ldb + n]  (B MN-major [K,N], e.g. W, V)
//   SCHEME=3: D += Ah*Bh + Ah*Bl + Al*Bh   (fp32-accurate)
//   SCHEME=2: D += Ah*Bt + Al*Bt           (A exact split, B rounded rna)
//   SCHEME=0: D += A*B, operands ALREADY tf32 bit patterns (no conversion)
//   EPI=0: fp32 out (*alpha, +bias)   EPI=1: rna-tf32-rounded out
// BM=BN=128, KC=32, 256 threads (8 warps, each 64x32).
// 3-stage cp.async pipeline, one __syncthreads per chunk.
// ---------------------------------------------------------------------------
#define A_TILE_F 4608            // 128 * 36 floats
#define B_TILE_F 4608            // >= max(128*36 direct, 32*136 trans)
#define STAGE_F  (A_TILE_F + B_TILE_F)
#define STAGES   3
#define GEMM_SMEM_BYTES (STAGES * STAGE_F * 4)   // 110592

template <bool TRANSB_LOAD, bool HASBIAS, int SCHEME, int EPI>
__device__ __forceinline__
void gemm_body(const float* __restrict__ A, const float* __restrict__ B,
               const float* __restrict__ bias, float* __restrict__ C,
               int K, int lda, int ldb, int ldc, float alpha,
               int row0, int col0)
{
    extern __shared__ float smem[];

    const int tid  = threadIdx.x;
    const int wid  = tid >> 5;
    const int lane = tid & 31;
    const int tg   = lane >> 2;      // 0..7
    const int tk   = lane & 3;       // 0..3
    const int wm   = (wid >> 2) * 64;   // warp m-offset in tile
    const int wn   = (wid & 3) * 32;    // warp n-offset in tile

    float acc[4][4][4];
#pragma unroll
    for (int mt = 0; mt < 4; mt++)
#pragma unroll
        for (int nt = 0; nt < 4; nt++)
#pragma unroll
            for (int e = 0; e < 4; e++) acc[mt][nt][e] = 0.0f;

    // ---- stage fill via cp.async ----
    auto fill = [&](int st, int k0) {
        float* base = smem + st * STAGE_F;
        const uint32_t sAa = smem_u32(base);
        const uint32_t sBa = smem_u32(base + A_TILE_F);
#pragma unroll
        for (int j = 0; j < 4; j++) {
            const int idx = tid + j * 256;
            const int r  = idx >> 3;
            const int c4 = (idx & 7) << 2;
            CP_ASYNC16(sAa + (uint32_t)(r * 36 + c4) * 4u,
                       A + (size_t)(row0 + r) * lda + k0 + c4);
        }
        if (TRANSB_LOAD) {
#pragma unroll
            for (int j = 0; j < 4; j++) {
                const int idx = tid + j * 256;
                const int kk = idx >> 5;
                const int n4 = (idx & 31) << 2;
                CP_ASYNC16(sBa + (uint32_t)(kk * 136 + n4) * 4u,
                           B + (size_t)(k0 + kk) * ldb + col0 + n4);
            }
        } else {
#pragma unroll
            for (int j = 0; j < 4; j++) {
                const int idx = tid + j * 256;
                const int r  = idx >> 3;
                const int c4 = (idx & 7) << 2;
                CP_ASYNC16(sBa + (uint32_t)(r * 36 + c4) * 4u,
                           B + (size_t)(col0 + r) * ldb + k0 + c4);
            }
        }
        CP_COMMIT();
    };

    // ---- compute one staged chunk (4 k8-steps) ----
    auto compute = [&](int st) {
        const float* sA = smem + st * STAGE_F;
        const float* sB = sA + A_TILE_F;
        const uint32_t* uA = (const uint32_t*)sA;
        const uint32_t* uB = (const uint32_t*)sB;
#pragma unroll
        for (int s = 0; s < 4; s++) {
            uint32_t bh[4][2], bl[4][2];
#pragma unroll
            for (int nt = 0; nt < 4; nt++) {
                const int n0 = wn + nt * 8;
                int i0, i1;
                if (TRANSB_LOAD) {
                    i0 = (s * 8 + tk)     * 136 + n0 + tg;
                    i1 = (s * 8 + tk + 4) * 136 + n0 + tg;
                } else {
                    i0 = (n0 + tg) * 36 + s * 8 + tk;
                    i1 = i0 + 4;
                }
                if (SCHEME == 3) {
                    split3(sB[i0], bh[nt][0], bl[nt][0]);
                    split3(sB[i1], bh[nt][1], bl[nt][1]);
                } else if (SCHEME == 2) {
                    bh[nt][0] = to_tf32(sB[i0]);
                    bh[nt][1] = to_tf32(sB[i1]);
                } else {  // SCHEME 0: already tf32 bits
                    bh[nt][0] = uB[i0];
                    bh[nt][1] = uB[i1];
                }
            }
#pragma unroll
            for (int mt = 0; mt < 4; mt++) {
                const int m0 = wm + mt * 16;
                const int i0 = (m0 + tg) * 36 + s * 8 + tk;
                const int i1 = i0 + 8 * 36;
                if (SCHEME == 0) {
                    uint32_t at[4];
                    at[0] = uA[i0];
                    at[1] = uA[i1];
                    at[2] = uA[i0 + 4];
                    at[3] = uA[i1 + 4];
#pragma unroll
                    for (int nt = 0; nt < 4; nt++) mma8(acc[mt][nt], at, bh[nt]);
                } else {
                    uint32_t ah[4], al[4];
                    split3(sA[i0],     ah[0], al[0]);
                    split3(sA[i1],     ah[1], al[1]);
                    split3(sA[i0 + 4], ah[2], al[2]);
                    split3(sA[i1 + 4], ah[3], al[3]);
#pragma unroll
                    for (int nt = 0; nt < 4; nt++) mma8(acc[mt][nt], ah, bh[nt]);
                    if (SCHEME == 3) {
#pragma unroll
                        for (int nt = 0; nt < 4; nt++) mma8(acc[mt][nt], ah, bl[nt]);
                    }
#pragma unroll
                    for (int nt = 0; nt < 4; nt++) mma8(acc[mt][nt], al, bh[nt]);
                }
            }
        }
    };

    // ---- 3-stage mainloop, one barrier per chunk ----
    const int nchunk = K >> 5;
    fill(0, 0);
    fill(1, 32);
    for (int i = 0; i < nchunk; i++) {
        if (i + 1 < nchunk) { CP_WAIT1(); }
        else                { CP_WAIT0(); }
        __syncthreads();
        if (i + 2 < nchunk) fill((i + 2) % STAGES, (i + 2) << 5);
        compute(i % STAGES);
    }

    // ---- epilogue ----
#pragma unroll
    for (int mt = 0; mt < 4; mt++) {
        const int r = row0 + wm + mt * 16 + tg;
#pragma unroll
        for (int nt = 0; nt < 4; nt++) {
            const int col = col0 + wn + nt * 8 + tk * 2;
            float v[4];
            v[0] = acc[mt][nt][0] * alpha;
            v[1] = acc[mt][nt][1] * alpha;
            v[2] = acc[mt][nt][2] * alpha;
            v[3] = acc[mt][nt][3] * alpha;
            if (HASBIAS) {
                const float b0 = bias[col], b1 = bias[col + 1];
                v[0] += b0; v[1] += b1;
                v[2] += b0; v[3] += b1;
            }
            float2 v0, v1;
            if (EPI == 1) {
                v0 = make_float2(__uint_as_float(to_tf32(v[0])),
                                 __uint_as_float(to_tf32(v[1])));
                v1 = make_float2(__uint_as_float(to_tf32(v[2])),
                                 __uint_as_float(to_tf32(v[3])));
            } else {
                v0 = make_float2(v[0], v[1]);
                v1 = make_float2(v[2], v[3]);
            }
            *(float2*)(C + (size_t)r * ldc + col)       = v0;
            *(float2*)(C + (size_t)(r + 8) * ldc + col) = v1;
        }
    }
}

// ---------------------------------------------------------------------------
// Kernel 1: Q,K projections (x3, bias, fp32 out). grid (8, 64, 2)
// ---------------------------------------------------------------------------
__global__ __launch_bounds__(256, 2)
void proj_qk_k(const float* __restrict__ q, const float* __restrict__ k,
               const float* __restrict__ Wq, const float* __restrict__ bq,
               const float* __restrict__ Wk, const float* __restrict__ bk,
               float* __restrict__ Q, float* __restrict__ K)
{
    const int row0 = blockIdx.y * 128;
    const int col0 = blockIdx.x * 128;
    if (blockIdx.z == 0)
        gemm_body<true, true, 3, 0>(q, Wq, bq, Q, DMODEL, DMODEL, DMODEL, DMODEL,
                                    1.0f, row0, col0);
    else
        gemm_body<true, true, 3, 0>(k, Wk, bk, K, DMODEL, DMODEL, DMODEL, DMODEL,
                                    1.0f, row0, col0);
}

// ---------------------------------------------------------------------------
// Kernel 2: scores (x3) + V projection (x2, tf32-rounded out) in ONE launch.
// grid (16, 16, 6): z<4 -> scores batch z (16x16 tiles);
// z in {4,5} -> V proj: idx = (z-4)*256 + y*16 + x over 512 tiles (8 cols).
// V-proj CTAs launch behind the scores CTAs and fill the tail waves.
// ---------------------------------------------------------------------------
__global__ __launch_bounds__(256, 2)
void scores_vproj_k(const float* __restrict__ Qg, const float* __restrict__ Kg,
                    float* __restrict__ Sg,
                    const float* __restrict__ v,
                    const float* __restrict__ Wv, const float* __restrict__ bv,
                    float* __restrict__ Vt)
{
    if (blockIdx.z < 4) {
        const long long zo = (long long)blockIdx.z * SEQ * DMODEL;
        gemm_body<false, false, 3, 0>(Qg + zo, Kg + zo, nullptr,
                                      Sg + (long long)blockIdx.z * SEQ * SEQ,
                                      DMODEL, DMODEL, DMODEL, SEQ, 8.0f,
                                      blockIdx.y * 128, blockIdx.x * 128);
    } else {
        const int idx  = (blockIdx.z - 4) * 256 + blockIdx.y * 16 + blockIdx.x;
        const int col0 = (idx & 7) * 128;
        const int row0 = (idx >> 3) * 128;
        gemm_body<true, true, 2, 1>(v, Wv, bv, Vt,
                                    DMODEL, DMODEL, DMODEL, DMODEL, 1.0f,
                                    row0, col0);
    }
}

// ---------------------------------------------------------------------------
// JAX threefry2x32, key (0,42), partitionable scheme:
//   bits[i] = y0 ^ y1 of threefry2x32(key, (0, i)); keep <=> MSB==0
// ---------------------------------------------------------------------------
__device__ __forceinline__ uint32_t threefry_mask_word(uint32_t idx)
{
    const uint32_t ks0 = 0u;
    const uint32_t ks1 = 42u;
    const uint32_t ks2 = 42u ^ 0x1BD11BDAu;
    uint32_t x0 = ks0;
    uint32_t x1 = idx + ks1;
#define TFR(r) { x0 += x1; x1 = __funnelshift_l(x1, x1, (r)); x1 ^= x0; }
    TFR(13) TFR(15) TFR(26) TFR(6)
    x0 += ks1; x1 += ks2 + 1u;
    TFR(17) TFR(29) TFR(16) TFR(24)
    x0 += ks2; x1 += ks0 + 2u;
    TFR(13) TFR(15) TFR(26) TFR(6)
    x0 += ks0; x1 += ks1 + 3u;
    TFR(17) TFR(29) TFR(16) TFR(24)
    x0 += ks1; x1 += ks2 + 4u;
    TFR(13) TFR(15) TFR(26) TFR(6)
    x0 += ks2; x1 += ks0 + 5u;
#undef TFR
    return x0 ^ x1;
}

// ---------------------------------------------------------------------------
// Kernel 3: softmax + dropout. Writes P PRE-ROUNDED to tf32 (rna) so the PV
// mainloop needs zero conversions. kept value scaled by 2 (1/(1-p)).
// ---------------------------------------------------------------------------
__global__ __launch_bounds__(256, 4)
void softmax_dropout_k(float* __restrict__ S)
{
    const int q   = blockIdx.x;
    const int b   = blockIdx.y;
    const int tid = threadIdx.x;
    float* __restrict__ row = S + ((size_t)b * SEQ + q) * SEQ;

    float a[8];
#pragma unroll
    for (int j = 0; j < 8; j++) a[j] = row[tid + j * 256];

    float m = a[0];
#pragma unroll
    for (int j = 1; j < 8; j++) m = fmaxf(m, a[j]);
#pragma unroll
    for (int s = 16; s > 0; s >>= 1)
        m = fmaxf(m, __shfl_xor_sync(0xffffffffu, m, s));
    __shared__ float red[8];
    const int wid = tid >> 5, lane = tid & 31;
    if (lane == 0) red[wid] = m;
    __syncthreads();
    m = red[0];
#pragma unroll
    for (int w = 1; w < 8; w++) m = fmaxf(m, red[w]);
    __syncthreads();

    float s0 = 0.0f;
#pragma unroll
    for (int j = 0; j < 8; j++) {
        a[j] = __expf(a[j] - m);
        s0 += a[j];
    }
#pragma unroll
    for (int s = 16; s > 0; s >>= 1)
        s0 += __shfl_xor_sync(0xffffffffu, s0, s);
    if (lane == 0) red[wid] = s0;
    __syncthreads();
    s0 = 0.0f;
#pragma unroll
    for (int w = 0; w < 8; w++) s0 += red[w];

    const float inv = 2.0f / s0;

    const uint32_t base = ((uint32_t)(b * SEQ + q)) * (uint32_t)SEQ;
#pragma unroll
    for (int j = 0; j < 8; j++) {
        const uint32_t k = (uint32_t)tid + (uint32_t)j * 256u;
        const uint32_t w = threefry_mask_word(base + k);
        const float val = (w >> 31) ? 0.0f : a[j] * inv;
        row[k] = __uint_as_float(to_tf32(val));
    }
}

// ---------------------------------------------------------------------------
// Kernel 4: O = P @ Vt, both operands pre-rounded tf32 bits -> SCHEME 0
// (conversion-free mainloop: LDS + MMA only). grid (8, 16, 4)
// ---------------------------------------------------------------------------
__global__ __launch_bounds__(256, 2)
void pv_k(const float* __restrict__ Pg, const float* __restrict__ Vt,
          float* __restrict__ Og)
{
    const long long z = blockIdx.z;
    gemm_body<true, false, 0, 0>(Pg + z * SEQ * SEQ, Vt + z * SEQ * DMODEL,
                                 nullptr, Og + z * SEQ * DMODEL,
                                 SEQ, SEQ, DMODEL, DMODEL, 1.0f,
                                 blockIdx.y * 128, blockIdx.x * 128);
}

// ---------------------------------------------------------------------------
// Launcher
// ---------------------------------------------------------------------------
extern "C" void kernel_launch(void* const* d_in, const int* in_sizes, int n_in,
                              void* d_out, int out_size)
{
    (void)in_sizes; (void)n_in; (void)out_size;
    const float* query = (const float*)d_in[0];
    const float* key_  = (const float*)d_in[1];
    const float* value = (const float*)d_in[2];
    const float* Wq    = (const float*)d_in[3];
    const float* bq    = (const float*)d_in[4];
    const float* Wk    = (const float*)d_in[5];
    const float* bk    = (const float*)d_in[6];
    const float* Wv    = (const float*)d_in[7];
    const float* bv    = (const float*)d_in[8];
    float* out = (float*)d_out;

    float *dQ, *dK, *dV, *dS;
    cudaGetSymbolAddress((void**)&dQ, g_Q);
    cudaGetSymbolAddress((void**)&dK, g_K);
    cudaGetSymbolAddress((void**)&dV, g_V);
    cudaGetSymbolAddress((void**)&dS, g_S);

    static bool attr_done = false;
    if (!attr_done) {
        cudaFuncSetAttribute(proj_qk_k,
                             cudaFuncAttributeMaxDynamicSharedMemorySize, GEMM_SMEM_BYTES);
        cudaFuncSetAttribute(scores_vproj_k,
                             cudaFuncAttributeMaxDynamicSharedMemorySize, GEMM_SMEM_BYTES);
        cudaFuncSetAttribute(pv_k,
                             cudaFuncAttributeMaxDynamicSharedMemorySize, GEMM_SMEM_BYTES);
        attr_done = true;
    }

    dim3 thr(256);

    // 1) Q,K projections (x3)
    dim3 gQK(DMODEL / 128, (BATCH * SEQ) / 128, 2);
    proj_qk_k<<<gQK, thr, GEMM_SMEM_BYTES>>>(query, key_, Wq, bq, Wk, bk, dQ, dK);

    // 2) Scores (x3) + V projection (x2, rounded out) — one launch,
    //    V-proj CTAs fill the scores tail waves
    dim3 gSV(16, 16, 6);
    scores_vproj_k<<<gSV, thr, GEMM_SMEM_BYTES>>>(dQ, dK, dS, value, Wv, bv, dV);

    // 3) Softmax + threefry dropout; P written pre-rounded to tf32
    dim3 gSm(SEQ, BATCH, 1);
    softmax_dropout_k<<<gSm, thr>>>(dS);

    // 4) O = P @ Vt (conversion-free x1)
    dim3 gOut(DMODEL / 128, SEQ / 128, BATCH);
    pv_k<<<gOut, thr, GEMM_SMEM_BYTES>>>(dS, dV, out);
}

// round 12
// speedup vs baseline: 1.4070x; 1.1105x over previous
#include <cuda_runtime.h>
#include <cuda_bf16.h>
#include <cstdint>

// ---------------------------------------------------------------------------
// Problem constants
// ---------------------------------------------------------------------------
#define BATCH  4
#define SEQ    2048
#define DMODEL 1024

// Scratch (device globals: allocation-free)
// Q,K live as PRE-SPLIT bf16 planes (hi+lo = fp32-equivalent, same bytes).
__device__ __nv_bfloat16 g_Qh[(size_t)BATCH * SEQ * DMODEL];
__device__ __nv_bfloat16 g_Ql[(size_t)BATCH * SEQ * DMODEL];
__device__ __nv_bfloat16 g_Kh[(size_t)BATCH * SEQ * DMODEL];
__device__ __nv_bfloat16 g_Kl[(size_t)BATCH * SEQ * DMODEL];
__device__ float g_V[(size_t)BATCH * SEQ * DMODEL];   // pre-rounded tf32 bits
__device__ float g_S[(size_t)BATCH * SEQ * SEQ];      // scores, then tf32 P

// ---------------------------------------------------------------------------
// Helpers
// ---------------------------------------------------------------------------
__device__ __forceinline__ uint32_t smem_u32(const void* p) {
    uint32_t a;
    asm("{ .reg .u64 t; cvta.to.shared.u64 t, %1; cvt.u32.u64 %0, t; }"
        : "=r"(a) : "l"(p));
    return a;
}

#define CP_ASYNC16(saddr, gptr) \
    asm volatile("cp.async.cg.shared.global [%0], [%1], 16;" \
        :: "r"(saddr), "l"(gptr) : "memory")
#define CP_COMMIT() asm volatile("cp.async.commit_group;" ::: "memory")
#define CP_WAIT0()  asm volatile("cp.async.wait_group 0;" ::: "memory")
#define CP_WAIT1()  asm volatile("cp.async.wait_group 1;" ::: "memory")

// tf32x3 split WITHOUT cvt: hi = top-10-mantissa truncation (valid tf32);
// lo passed as raw fp32 bits (HMMA truncates to tf32 subset in HW).
__device__ __forceinline__ void split3(float x, uint32_t& hi, uint32_t& lo) {
    const uint32_t h = __float_as_uint(x) & 0xffffe000u;
    hi = h;
    lo = __float_as_uint(x - __uint_as_float(h));
}

// Proper rna rounding (single-rounding operands: quality is first-order)
__device__ __forceinline__ uint32_t to_tf32(float x) {
    uint32_t t;
    asm("cvt.rna.tf32.f32 %0, %1;" : "=r"(t) : "f"(x));
    return t;
}

// D += A(16x8 tf32) * B(8x8 tf32), fp32 accumulate
__device__ __forceinline__ void mma8(float* d, const uint32_t* a, const uint32_t* b) {
    asm volatile(
        "mma.sync.aligned.m16n8k8.row.col.f32.tf32.tf32.f32 "
        "{%0,%1,%2,%3}, {%4,%5,%6,%7}, {%8,%9}, {%0,%1,%2,%3};"
        : "+f"(d[0]), "+f"(d[1]), "+f"(d[2]), "+f"(d[3])
        : "r"(a[0]), "r"(a[1]), "r"(a[2]), "r"(a[3]), "r"(b[0]), "r"(b[1]));
}

// D += A(16x16 bf16) * B(16x8 bf16), fp32 accumulate — 2x K per instruction
__device__ __forceinline__ void mma16bf(float* d, const uint32_t* a, const uint32_t* b) {
    asm volatile(
        "mma.sync.aligned.m16n8k16.row.col.f32.bf16.bf16.f32 "
        "{%0,%1,%2,%3}, {%4,%5,%6,%7}, {%8,%9}, {%0,%1,%2,%3};"
        : "+f"(d[0]), "+f"(d[1]), "+f"(d[2]), "+f"(d[3])
        : "r"(a[0]), "r"(a[1]), "r"(a[2]), "r"(a[3]), "r"(b[0]), "r"(b[1]));
}

// ---------------------------------------------------------------------------
// tf32 emulated GEMM body (proj / vproj / pv).
//   TRANSB_LOAD=false: Bmat[k,n] = B[n*ldb + k]
//   TRANSB_LOAD=true : Bmat[k,n] = B[k*ldb + n]
//   SCHEME=3: D += Ah*Bh + Ah*Bl + Al*Bh
//   SCHEME=2: D += Ah*Bt + Al*Bt (B rounded rna)
//   SCHEME=0: D += A*B, operands already tf32 bits
//   EPI=0: fp32 out  EPI=1: rna-tf32 out  EPI=3: bf16 hi/lo plane out
// ---------------------------------------------------------------------------
#define A_TILE_F 4608            // 128 * 36 floats
#define B_TILE_F 4608
#define STAGE_F  (A_TILE_F + B_TILE_F)
#define STAGES   3
#define GEMM_SMEM_BYTES (STAGES * STAGE_F * 4)   // 110592

template <bool TRANSB_LOAD, bool HASBIAS, int SCHEME, int EPI>
__device__ __forceinline__
void gemm_body(const float* __restrict__ A, const float* __restrict__ B,
               const float* __restrict__ bias, float* __restrict__ C,
               __nv_bfloat16* __restrict__ Cbh, __nv_bfloat16* __restrict__ Cbl,
               int K, int lda, int ldb, int ldc, float alpha,
               int row0, int col0)
{
    extern __shared__ float smem[];

    const int tid  = threadIdx.x;
    const int wid  = tid >> 5;
    const int lane = tid & 31;
    const int tg   = lane >> 2;
    const int tk   = lane & 3;
    const int wm   = (wid >> 2) * 64;
    const int wn   = (wid & 3) * 32;

    float acc[4][4][4];
#pragma unroll
    for (int mt = 0; mt < 4; mt++)
#pragma unroll
        for (int nt = 0; nt < 4; nt++)
#pragma unroll
            for (int e = 0; e < 4; e++) acc[mt][nt][e] = 0.0f;

    auto fill = [&](int st, int k0) {
        float* base = smem + st * STAGE_F;
        const uint32_t sAa = smem_u32(base);
        const uint32_t sBa = smem_u32(base + A_TILE_F);
#pragma unroll
        for (int j = 0; j < 4; j++) {
            const int idx = tid + j * 256;
            const int r  = idx >> 3;
            const int c4 = (idx & 7) << 2;
            CP_ASYNC16(sAa + (uint32_t)(r * 36 + c4) * 4u,
                       A + (size_t)(row0 + r) * lda + k0 + c4);
        }
        if (TRANSB_LOAD) {
#pragma unroll
            for (int j = 0; j < 4; j++) {
                const int idx = tid + j * 256;
                const int kk = idx >> 5;
                const int n4 = (idx & 31) << 2;
                CP_ASYNC16(sBa + (uint32_t)(kk * 136 + n4) * 4u,
                           B + (size_t)(k0 + kk) * ldb + col0 + n4);
            }
        } else {
#pragma unroll
            for (int j = 0; j < 4; j++) {
                const int idx = tid + j * 256;
                const int r  = idx >> 3;
                const int c4 = (idx & 7) << 2;
                CP_ASYNC16(sBa + (uint32_t)(r * 36 + c4) * 4u,
                           B + (size_t)(col0 + r) * ldb + k0 + c4);
            }
        }
        CP_COMMIT();
    };

    auto compute = [&](int st) {
        const float* sA = smem + st * STAGE_F;
        const float* sB = sA + A_TILE_F;
        const uint32_t* uA = (const uint32_t*)sA;
        const uint32_t* uB = (const uint32_t*)sB;
#pragma unroll
        for (int s = 0; s < 4; s++) {
            uint32_t bh[4][2], bl[4][2];
#pragma unroll
            for (int nt = 0; nt < 4; nt++) {
                const int n0 = wn + nt * 8;
                int i0, i1;
                if (TRANSB_LOAD) {
                    i0 = (s * 8 + tk)     * 136 + n0 + tg;
                    i1 = (s * 8 + tk + 4) * 136 + n0 + tg;
                } else {
                    i0 = (n0 + tg) * 36 + s * 8 + tk;
                    i1 = i0 + 4;
                }
                if (SCHEME == 3) {
                    split3(sB[i0], bh[nt][0], bl[nt][0]);
                    split3(sB[i1], bh[nt][1], bl[nt][1]);
                } else if (SCHEME == 2) {
                    bh[nt][0] = to_tf32(sB[i0]);
                    bh[nt][1] = to_tf32(sB[i1]);
                } else {
                    bh[nt][0] = uB[i0];
                    bh[nt][1] = uB[i1];
                }
            }
#pragma unroll
            for (int mt = 0; mt < 4; mt++) {
                const int m0 = wm + mt * 16;
                const int i0 = (m0 + tg) * 36 + s * 8 + tk;
                const int i1 = i0 + 8 * 36;
                if (SCHEME == 0) {
                    uint32_t at[4];
                    at[0] = uA[i0];
                    at[1] = uA[i1];
                    at[2] = uA[i0 + 4];
                    at[3] = uA[i1 + 4];
#pragma unroll
                    for (int nt = 0; nt < 4; nt++) mma8(acc[mt][nt], at, bh[nt]);
                } else {
                    uint32_t ah[4], al[4];
                    split3(sA[i0],     ah[0], al[0]);
                    split3(sA[i1],     ah[1], al[1]);
                    split3(sA[i0 + 4], ah[2], al[2]);
                    split3(sA[i1 + 4], ah[3], al[3]);
#pragma unroll
                    for (int nt = 0; nt < 4; nt++) mma8(acc[mt][nt], ah, bh[nt]);
                    if (SCHEME == 3) {
#pragma unroll
                        for (int nt = 0; nt < 4; nt++) mma8(acc[mt][nt], ah, bl[nt]);
                    }
#pragma unroll
                    for (int nt = 0; nt < 4; nt++) mma8(acc[mt][nt], al, bh[nt]);
                }
            }
        }
    };

    const int nchunk = K >> 5;
    fill(0, 0);
    fill(1, 32);
    for (int i = 0; i < nchunk; i++) {
        if (i + 1 < nchunk) { CP_WAIT1(); }
        else                { CP_WAIT0(); }
        __syncthreads();
        if (i + 2 < nchunk) fill((i + 2) % STAGES, (i + 2) << 5);
        compute(i % STAGES);
    }

    // ---- epilogue ----
#pragma unroll
    for (int mt = 0; mt < 4; mt++) {
        const int r = row0 + wm + mt * 16 + tg;
#pragma unroll
        for (int nt = 0; nt < 4; nt++) {
            const int col = col0 + wn + nt * 8 + tk * 2;
            float v[4];
            v[0] = acc[mt][nt][0] * alpha;
            v[1] = acc[mt][nt][1] * alpha;
            v[2] = acc[mt][nt][2] * alpha;
            v[3] = acc[mt][nt][3] * alpha;
            if (HASBIAS) {
                const float b0 = bias[col], b1 = bias[col + 1];
                v[0] += b0; v[1] += b1;
                v[2] += b0; v[3] += b1;
            }
            if (EPI == 3) {
                // split each value into bf16 hi + bf16 lo (hi+lo ~ 2^-18 rel)
                __nv_bfloat16 h0 = __float2bfloat16_rn(v[0]);
                __nv_bfloat16 h1 = __float2bfloat16_rn(v[1]);
                __nv_bfloat16 h2 = __float2bfloat16_rn(v[2]);
                __nv_bfloat16 h3 = __float2bfloat16_rn(v[3]);
                __nv_bfloat16 l0 = __float2bfloat16_rn(v[0] - __bfloat162float(h0));
                __nv_bfloat16 l1 = __float2bfloat16_rn(v[1] - __bfloat162float(h1));
                __nv_bfloat16 l2 = __float2bfloat16_rn(v[2] - __bfloat162float(h2));
                __nv_bfloat16 l3 = __float2bfloat16_rn(v[3] - __bfloat162float(h3));
                __nv_bfloat162 ph0; ph0.x = h0; ph0.y = h1;
                __nv_bfloat162 pl0; pl0.x = l0; pl0.y = l1;
                __nv_bfloat162 ph1; ph1.x = h2; ph1.y = h3;
                __nv_bfloat162 pl1; pl1.x = l2; pl1.y = l3;
                *(__nv_bfloat162*)(Cbh + (size_t)r * ldc + col)       = ph0;
                *(__nv_bfloat162*)(Cbl + (size_t)r * ldc + col)       = pl0;
                *(__nv_bfloat162*)(Cbh + (size_t)(r + 8) * ldc + col) = ph1;
                *(__nv_bfloat162*)(Cbl + (size_t)(r + 8) * ldc + col) = pl1;
            } else {
                float2 v0, v1;
                if (EPI == 1) {
                    v0 = make_float2(__uint_as_float(to_tf32(v[0])),
                                     __uint_as_float(to_tf32(v[1])));
                    v1 = make_float2(__uint_as_float(to_tf32(v[2])),
                                     __uint_as_float(to_tf32(v[3])));
                } else {
                    v0 = make_float2(v[0], v[1]);
                    v1 = make_float2(v[2], v[3]);
                }
                *(float2*)(C + (size_t)r * ldc + col)       = v0;
                *(float2*)(C + (size_t)(r + 8) * ldc + col) = v1;
            }
        }
    }
}

// ---------------------------------------------------------------------------
// Scores body: bf16x3 on pre-split planes (Qh,Ql,Kh,Kl), m16n8k16 MMAs.
// S = alpha * (QhKh + QhKl + QlKh). KC=32 (2 k16-steps/chunk), 2-stage.
// Plane rows padded to 80B (20 words) — conflict-free LDS.32 fragments.
// ---------------------------------------------------------------------------
#define SC_ROWW    20                    // uint32 words per row per plane
#define SC_PLANE_W (128 * SC_ROWW)       // 2560 words
#define SC_STAGE_W (4 * SC_PLANE_W)      // 10240 words
#define SCORES_SMEM_BYTES (2 * SC_STAGE_W * 4)   // 81920

__device__ __forceinline__
void scores_body(const __nv_bfloat16* __restrict__ Qh,
                 const __nv_bfloat16* __restrict__ Ql,
                 const __nv_bfloat16* __restrict__ Kh,
                 const __nv_bfloat16* __restrict__ Kl,
                 float* __restrict__ Sg, float alpha, int row0, int col0)
{
    extern __shared__ float smemf[];
    uint32_t* sm = (uint32_t*)smemf;

    const int tid  = threadIdx.x;
    const int wid  = tid >> 5;
    const int lane = tid & 31;
    const int tg   = lane >> 2;
    const int tk   = lane & 3;
    const int wm   = (wid >> 2) * 64;
    const int wn   = (wid & 3) * 32;

    float acc[4][4][4];
#pragma unroll
    for (int mt = 0; mt < 4; mt++)
#pragma unroll
        for (int nt = 0; nt < 4; nt++)
#pragma unroll
            for (int e = 0; e < 4; e++) acc[mt][nt][e] = 0.0f;

    // chunk = 32 k-elems = 64 bytes/row/plane = 4 x 16B
    auto fill = [&](int st, int k0) {
        const uint32_t base = smem_u32(sm + st * SC_STAGE_W);
#pragma unroll
        for (int j = 0; j < 8; j++) {
            const __nv_bfloat16* src = (j < 2) ? Qh : ((j < 4) ? Ql : ((j < 6) ? Kh : Kl));
            const int rb   = (j < 4) ? row0 : col0;
            const int pl   = j >> 1;
            const int t    = tid + (j & 1) * 256;     // 0..511
            const int r    = t >> 2;                  // 0..127
            const int c16  = t & 3;                   // 16B chunk within row
            CP_ASYNC16(base + (uint32_t)(pl * SC_PLANE_W + r * SC_ROWW + c16 * 4) * 4u,
                       src + (size_t)(rb + r) * DMODEL + k0 + c16 * 8);
        }
        CP_COMMIT();
    };

    auto compute = [&](int st) {
        const uint32_t* sAh = sm + st * SC_STAGE_W;
        const uint32_t* sAl = sAh + SC_PLANE_W;
        const uint32_t* sBh = sAl + SC_PLANE_W;
        const uint32_t* sBl = sBh + SC_PLANE_W;
#pragma unroll
        for (int s = 0; s < 2; s++) {          // two k16-steps per chunk
            uint32_t bh[4][2], bl[4][2];
#pragma unroll
            for (int nt = 0; nt < 4; nt++) {
                const int i0 = (wn + nt * 8 + tg) * SC_ROWW + s * 8 + tk;
                bh[nt][0] = sBh[i0]; bh[nt][1] = sBh[i0 + 4];
                bl[nt][0] = sBl[i0]; bl[nt][1] = sBl[i0 + 4];
            }
#pragma unroll
            for (int mt = 0; mt < 4; mt++) {
                const int r0i = (wm + mt * 16 + tg) * SC_ROWW + s * 8 + tk;
                const int r1i = r0i + 8 * SC_ROWW;
                uint32_t ah[4], al[4];
                ah[0] = sAh[r0i];     ah[1] = sAh[r1i];
                ah[2] = sAh[r0i + 4]; ah[3] = sAh[r1i + 4];
                al[0] = sAl[r0i];     al[1] = sAl[r1i];
                al[2] = sAl[r0i + 4]; al[3] = sAl[r1i + 4];
#pragma unroll
                for (int nt = 0; nt < 4; nt++) mma16bf(acc[mt][nt], ah, bh[nt]);
#pragma unroll
                for (int nt = 0; nt < 4; nt++) mma16bf(acc[mt][nt], ah, bl[nt]);
#pragma unroll
                for (int nt = 0; nt < 4; nt++) mma16bf(acc[mt][nt], al, bh[nt]);
            }
        }
    };

    const int nchunk = DMODEL / 32;   // 32
    fill(0, 0);
    for (int i = 0; i < nchunk; i++) {
        CP_WAIT0();
        __syncthreads();
        if (i + 1 < nchunk) fill((i + 1) & 1, (i + 1) * 32);
        compute(i & 1);
    }

    // epilogue: fp32 * alpha
#pragma unroll
    for (int mt = 0; mt < 4; mt++) {
        const int r = row0 + wm + mt * 16 + tg;
#pragma unroll
        for (int nt = 0; nt < 4; nt++) {
            const int col = col0 + wn + nt * 8 + tk * 2;
            *(float2*)(Sg + (size_t)r * SEQ + col) =
                make_float2(acc[mt][nt][0] * alpha, acc[mt][nt][1] * alpha);
            *(float2*)(Sg + (size_t)(r + 8) * SEQ + col) =
                make_float2(acc[mt][nt][2] * alpha, acc[mt][nt][3] * alpha);
        }
    }
}

// ---------------------------------------------------------------------------
// Kernel 1: Q,K projections (tf32x3, bias), epilogue -> bf16 hi/lo planes
// ---------------------------------------------------------------------------
__global__ __launch_bounds__(256, 2)
void proj_qk_k(const float* __restrict__ q, const float* __restrict__ k,
               const float* __restrict__ Wq, const float* __restrict__ bq,
               const float* __restrict__ Wk, const float* __restrict__ bk,
               __nv_bfloat16* __restrict__ Qh, __nv_bfloat16* __restrict__ Ql,
               __nv_bfloat16* __restrict__ Kh, __nv_bfloat16* __restrict__ Kl)
{
    const int row0 = blockIdx.y * 128;
    const int col0 = blockIdx.x * 128;
    if (blockIdx.z == 0)
        gemm_body<true, true, 3, 3>(q, Wq, bq, nullptr, Qh, Ql,
                                    DMODEL, DMODEL, DMODEL, DMODEL, 1.0f, row0, col0);
    else
        gemm_body<true, true, 3, 3>(k, Wk, bk, nullptr, Kh, Kl,
                                    DMODEL, DMODEL, DMODEL, DMODEL, 1.0f, row0, col0);
}

// ---------------------------------------------------------------------------
// Kernel 2: scores (bf16x3) + V projection (tf32x2, rounded out), one launch
// ---------------------------------------------------------------------------
__global__ __launch_bounds__(256, 2)
void scores_vproj_k(const __nv_bfloat16* __restrict__ Qh,
                    const __nv_bfloat16* __restrict__ Ql,
                    const __nv_bfloat16* __restrict__ Kh,
                    const __nv_bfloat16* __restrict__ Kl,
                    float* __restrict__ Sg,
                    const float* __restrict__ v,
                    const float* __restrict__ Wv, const float* __restrict__ bv,
                    float* __restrict__ Vt)
{
    if (blockIdx.z < 4) {
        const long long zo = (long long)blockIdx.z * SEQ * DMODEL;
        scores_body(Qh + zo, Ql + zo, Kh + zo, Kl + zo,
                    Sg + (long long)blockIdx.z * SEQ * SEQ, 8.0f,
                    blockIdx.y * 128, blockIdx.x * 128);
    } else {
        const int idx  = (blockIdx.z - 4) * 256 + blockIdx.y * 16 + blockIdx.x;
        const int col0 = (idx & 7) * 128;
        const int row0 = (idx >> 3) * 128;
        gemm_body<true, true, 2, 1>(v, Wv, bv, Vt, nullptr, nullptr,
                                    DMODEL, DMODEL, DMODEL, DMODEL, 1.0f,
                                    row0, col0);
    }
}

// ---------------------------------------------------------------------------
// JAX threefry2x32, key (0,42), partitionable scheme
// ---------------------------------------------------------------------------
__device__ __forceinline__ uint32_t threefry_mask_word(uint32_t idx)
{
    const uint32_t ks0 = 0u;
    const uint32_t ks1 = 42u;
    const uint32_t ks2 = 42u ^ 0x1BD11BDAu;
    uint32_t x0 = ks0;
    uint32_t x1 = idx + ks1;
#define TFR(r) { x0 += x1; x1 = __funnelshift_l(x1, x1, (r)); x1 ^= x0; }
    TFR(13) TFR(15) TFR(26) TFR(6)
    x0 += ks1; x1 += ks2 + 1u;
    TFR(17) TFR(29) TFR(16) TFR(24)
    x0 += ks2; x1 += ks0 + 2u;
    TFR(13) TFR(15) TFR(26) TFR(6)
    x0 += ks0; x1 += ks1 + 3u;
    TFR(17) TFR(29) TFR(16) TFR(24)
    x0 += ks1; x1 += ks2 + 4u;
    TFR(13) TFR(15) TFR(26) TFR(6)
    x0 += ks2; x1 += ks0 + 5u;
#undef TFR
    return x0 ^ x1;
}

// ---------------------------------------------------------------------------
// Kernel 3: softmax + dropout; P written pre-rounded tf32 (PV is conversion-free)
// ---------------------------------------------------------------------------
__global__ __launch_bounds__(256, 4)
void softmax_dropout_k(float* __restrict__ S)
{
    const int q   = blockIdx.x;
    const int b   = blockIdx.y;
    const int tid = threadIdx.x;
    float* __restrict__ row = S + ((size_t)b * SEQ + q) * SEQ;

    float a[8];
#pragma unroll
    for (int j = 0; j < 8; j++) a[j] = row[tid + j * 256];

    float m = a[0];
#pragma unroll
    for (int j = 1; j < 8; j++) m = fmaxf(m, a[j]);
#pragma unroll
    for (int s = 16; s > 0; s >>= 1)
        m = fmaxf(m, __shfl_xor_sync(0xffffffffu, m, s));
    __shared__ float red[8];
    const int wid = tid >> 5, lane = tid & 31;
    if (lane == 0) red[wid] = m;
    __syncthreads();
    m = red[0];
#pragma unroll
    for (int w = 1; w < 8; w++) m = fmaxf(m, red[w]);
    __syncthreads();

    float s0 = 0.0f;
#pragma unroll
    for (int j = 0; j < 8; j++) {
        a[j] = __expf(a[j] - m);
        s0 += a[j];
    }
#pragma unroll
    for (int s = 16; s > 0; s >>= 1)
        s0 += __shfl_xor_sync(0xffffffffu, s0, s);
    if (lane == 0) red[wid] = s0;
    __syncthreads();
    s0 = 0.0f;
#pragma unroll
    for (int w = 0; w < 8; w++) s0 += red[w];

    const float inv = 2.0f / s0;

    const uint32_t base = ((uint32_t)(b * SEQ + q)) * (uint32_t)SEQ;
#pragma unroll
    for (int j = 0; j < 8; j++) {
        const uint32_t k = (uint32_t)tid + (uint32_t)j * 256u;
        const uint32_t w = threefry_mask_word(base + k);
        const float val = (w >> 31) ? 0.0f : a[j] * inv;
        row[k] = __uint_as_float(to_tf32(val));
    }
}

// ---------------------------------------------------------------------------
// Kernel 4: O = P @ Vt, tf32 x1, conversion-free (operands pre-rounded)
// ---------------------------------------------------------------------------
__global__ __launch_bounds__(256, 2)
void pv_k(const float* __restrict__ Pg, const float* __restrict__ Vt,
          float* __restrict__ Og)
{
    const long long z = blockIdx.z;
    gemm_body<true, false, 0, 0>(Pg + z * SEQ * SEQ, Vt + z * SEQ * DMODEL,
                                 nullptr, Og + z * SEQ * DMODEL, nullptr, nullptr,
                                 SEQ, SEQ, DMODEL, DMODEL, 1.0f,
                                 blockIdx.y * 128, blockIdx.x * 128);
}

// ---------------------------------------------------------------------------
// Launcher
// ---------------------------------------------------------------------------
extern "C" void kernel_launch(void* const* d_in, const int* in_sizes, int n_in,
                              void* d_out, int out_size)
{
    (void)in_sizes; (void)n_in; (void)out_size;
    const float* query = (const float*)d_in[0];
    const float* key_  = (const float*)d_in[1];
    const float* value = (const float*)d_in[2];
    const float* Wq    = (const float*)d_in[3];
    const float* bq    = (const float*)d_in[4];
    const float* Wk    = (const float*)d_in[5];
    const float* bk    = (const float*)d_in[6];
    const float* Wv    = (const float*)d_in[7];
    const float* bv    = (const float*)d_in[8];
    float* out = (float*)d_out;

    __nv_bfloat16 *dQh, *dQl, *dKh, *dKl;
    float *dV, *dS;
    cudaGetSymbolAddress((void**)&dQh, g_Qh);
    cudaGetSymbolAddress((void**)&dQl, g_Ql);
    cudaGetSymbolAddress((void**)&dKh, g_Kh);
    cudaGetSymbolAddress((void**)&dKl, g_Kl);
    cudaGetSymbolAddress((void**)&dV,  g_V);
    cudaGetSymbolAddress((void**)&dS,  g_S);

    static bool attr_done = false;
    if (!attr_done) {
        cudaFuncSetAttribute(proj_qk_k,
                             cudaFuncAttributeMaxDynamicSharedMemorySize, GEMM_SMEM_BYTES);
        cudaFuncSetAttribute(scores_vproj_k,
                             cudaFuncAttributeMaxDynamicSharedMemorySize, GEMM_SMEM_BYTES);
        cudaFuncSetAttribute(pv_k,
                             cudaFuncAttributeMaxDynamicSharedMemorySize, GEMM_SMEM_BYTES);
        attr_done = true;
    }

    dim3 thr(256);

    // 1) Q,K projections (tf32x3) -> bf16 hi/lo planes
    dim3 gQK(DMODEL / 128, (BATCH * SEQ) / 128, 2);
    proj_qk_k<<<gQK, thr, GEMM_SMEM_BYTES>>>(query, key_, Wq, bq, Wk, bk,
                                             dQh, dQl, dKh, dKl);

    // 2) Scores (bf16x3, half the MMA cycles) + V projection tail-fill
    dim3 gSV(16, 16, 6);
    scores_vproj_k<<<gSV, thr, GEMM_SMEM_BYTES>>>(dQh, dQl, dKh, dKl, dS,
                                                  value, Wv, bv, dV);

    // 3) Softmax + threefry dropout; P pre-rounded tf32
    dim3 gSm(SEQ, BATCH, 1);
    softmax_dropout_k<<<gSm, thr>>>(dS);

    // 4) O = P @ Vt (conversion-free tf32 x1)
    dim3 gOut(DMODEL / 128, SEQ / 128, BATCH);
    pv_k<<<gOut, thr, GEMM_SMEM_BYTES>>>(dS, dV, out);
}

// round 13
// speedup vs baseline: 1.6011x; 1.1380x over previous
#include <cuda_runtime.h>
#include <cuda_bf16.h>
#include <cstdint>

// ---------------------------------------------------------------------------
// Problem constants
// ---------------------------------------------------------------------------
#define BATCH  4
#define SEQ    2048
#define DMODEL 1024
#define INELEM ((size_t)BATCH * SEQ * DMODEL)   // 8388608
#define WELEM  ((size_t)DMODEL * DMODEL)        // 1048576

// Scratch (device globals: allocation-free)
// Pre-split bf16 planes of the raw inputs (k-contiguous, layout unchanged)
__device__ __nv_bfloat16 g_INh[3 * INELEM];
__device__ __nv_bfloat16 g_INl[3 * INELEM];
// Pre-split + TRANSPOSED W planes: Wt[n][k] (k-contiguous)
__device__ __nv_bfloat16 g_Wh[3 * WELEM];
__device__ __nv_bfloat16 g_Wl[3 * WELEM];
// Projected Q,K as bf16 hi/lo planes
__device__ __nv_bfloat16 g_Qh[INELEM];
__device__ __nv_bfloat16 g_Ql[INELEM];
__device__ __nv_bfloat16 g_Kh[INELEM];
__device__ __nv_bfloat16 g_Kl[INELEM];
__device__ float g_V[INELEM];       // V projection, pre-rounded tf32 bits
__device__ float g_S[(size_t)BATCH * SEQ * SEQ];   // scores, then tf32 P

// ---------------------------------------------------------------------------
// Helpers
// ---------------------------------------------------------------------------
__device__ __forceinline__ uint32_t smem_u32(const void* p) {
    uint32_t a;
    asm("{ .reg .u64 t; cvta.to.shared.u64 t, %1; cvt.u32.u64 %0, t; }"
        : "=r"(a) : "l"(p));
    return a;
}

#define CP_ASYNC16(saddr, gptr) \
    asm volatile("cp.async.cg.shared.global [%0], [%1], 16;" \
        :: "r"(saddr), "l"(gptr) : "memory")
#define CP_COMMIT() asm volatile("cp.async.commit_group;" ::: "memory")
#define CP_WAIT0()  asm volatile("cp.async.wait_group 0;" ::: "memory")
#define CP_WAIT1()  asm volatile("cp.async.wait_group 1;" ::: "memory")

__device__ __forceinline__ uint32_t to_tf32(float x) {
    uint32_t t;
    asm("cvt.rna.tf32.f32 %0, %1;" : "=r"(t) : "f"(x));
    return t;
}

// bf16 hi/lo split (hi+lo captures ~16 mantissa bits, rel ~2^-17)
__device__ __forceinline__ void split_bf16(float x, __nv_bfloat16& h, __nv_bfloat16& l) {
    h = __float2bfloat16_rn(x);
    l = __float2bfloat16_rn(x - __bfloat162float(h));
}

// D += A(16x8 tf32) * B(8x8 tf32), fp32 accumulate
__device__ __forceinline__ void mma8(float* d, const uint32_t* a, const uint32_t* b) {
    asm volatile(
        "mma.sync.aligned.m16n8k8.row.col.f32.tf32.tf32.f32 "
        "{%0,%1,%2,%3}, {%4,%5,%6,%7}, {%8,%9}, {%0,%1,%2,%3};"
        : "+f"(d[0]), "+f"(d[1]), "+f"(d[2]), "+f"(d[3])
        : "r"(a[0]), "r"(a[1]), "r"(a[2]), "r"(a[3]), "r"(b[0]), "r"(b[1]));
}

// D += A(16x16 bf16) * B(16x8 bf16), fp32 accumulate — 2x K per instruction
__device__ __forceinline__ void mma16bf(float* d, const uint32_t* a, const uint32_t* b) {
    asm volatile(
        "mma.sync.aligned.m16n8k16.row.col.f32.bf16.bf16.f32 "
        "{%0,%1,%2,%3}, {%4,%5,%6,%7}, {%8,%9}, {%0,%1,%2,%3};"
        : "+f"(d[0]), "+f"(d[1]), "+f"(d[2]), "+f"(d[3])
        : "r"(a[0]), "r"(a[1]), "r"(a[2]), "r"(a[3]), "r"(b[0]), "r"(b[1]));
}

// ===========================================================================
// Pre-pass 1: split query/key/value (fp32) -> bf16 hi/lo planes (same layout)
// ===========================================================================
__global__ __launch_bounds__(256)
void split_in_k(const float* __restrict__ q, const float* __restrict__ k,
                const float* __restrict__ v,
                __nv_bfloat16* __restrict__ oh, __nv_bfloat16* __restrict__ ol)
{
    const float* src = (blockIdx.z == 0) ? q : ((blockIdx.z == 1) ? k : v);
    const size_t base = (size_t)blockIdx.z * INELEM;
    const size_t i = ((size_t)blockIdx.x * 256 + threadIdx.x) * 4;
    float4 x = *(const float4*)(src + i);
    __nv_bfloat16 h0, h1, h2, h3, l0, l1, l2, l3;
    split_bf16(x.x, h0, l0);
    split_bf16(x.y, h1, l1);
    split_bf16(x.z, h2, l2);
    split_bf16(x.w, h3, l3);
    __nv_bfloat162 ph0; ph0.x = h0; ph0.y = h1;
    __nv_bfloat162 ph1; ph1.x = h2; ph1.y = h3;
    __nv_bfloat162 pl0; pl0.x = l0; pl0.y = l1;
    __nv_bfloat162 pl1; pl1.x = l2; pl1.y = l3;
    *(__nv_bfloat162*)(oh + base + i)     = ph0;
    *(__nv_bfloat162*)(oh + base + i + 2) = ph1;
    *(__nv_bfloat162*)(ol + base + i)     = pl0;
    *(__nv_bfloat162*)(ol + base + i + 2) = pl1;
}

// ===========================================================================
// Pre-pass 2: transpose + split W[k][n] -> Wt planes [n][k] (k-contiguous)
// 32x32 tiles, block (32,8)
// ===========================================================================
__global__ __launch_bounds__(256)
void split_w_k(const float* __restrict__ Wq, const float* __restrict__ Wk,
               const float* __restrict__ Wv,
               __nv_bfloat16* __restrict__ oh, __nv_bfloat16* __restrict__ ol)
{
    const float* W = (blockIdx.z == 0) ? Wq : ((blockIdx.z == 1) ? Wk : Wv);
    const size_t base = (size_t)blockIdx.z * WELEM;
    __shared__ float t[32][33];
    const int kb = blockIdx.y * 32;   // k tile base (row of W)
    const int nb = blockIdx.x * 32;   // n tile base (col of W)
    const int tx = threadIdx.x, ty = threadIdx.y;
#pragma unroll
    for (int j = 0; j < 4; j++)
        t[ty + 8 * j][tx] = W[(size_t)(kb + ty + 8 * j) * DMODEL + nb + tx];
    __syncthreads();
#pragma unroll
    for (int j = 0; j < 4; j++) {
        const float val = t[tx][ty + 8 * j];
        __nv_bfloat16 h, l;
        split_bf16(val, h, l);
        const size_t o = base + (size_t)(nb + ty + 8 * j) * DMODEL + kb + tx;
        oh[o] = h;
        ol[o] = l;
    }
}

// ===========================================================================
// bf16x3 GEMM body: C[m,n] = alpha*(AhBh + AhBl + AlBh)[m,n] (+ bias[n])
// A planes [Mrows, K] k-contig (base row0), B planes [Nrows, K] k-contig
// (base col0). KC=32 (2 k16-steps), 2-stage, 256 thr, 8 warps 64x32.
//   EPI=0: fp32 * alpha          EPI=1: +bias, rna-tf32 out
//   EPI=3: +bias, bf16 hi/lo plane out
// ===========================================================================
#define SC_ROWW    20                    // uint32 words per row per plane
#define SC_PLANE_W (128 * SC_ROWW)       // 2560 words
#define SC_STAGE_W (4 * SC_PLANE_W)      // 10240 words
#define BF3_SMEM_BYTES (2 * SC_STAGE_W * 4)   // 81920

template <int EPI, bool HASBIAS>
__device__ __forceinline__
void bf3_body(const __nv_bfloat16* __restrict__ Ah,
              const __nv_bfloat16* __restrict__ Al,
              const __nv_bfloat16* __restrict__ Bh,
              const __nv_bfloat16* __restrict__ Bl,
              const float* __restrict__ bias,
              float* __restrict__ C,
              __nv_bfloat16* __restrict__ Cbh, __nv_bfloat16* __restrict__ Cbl,
              int K, int ldk, int ldc, float alpha, int row0, int col0)
{
    extern __shared__ float smemf[];
    uint32_t* sm = (uint32_t*)smemf;

    const int tid  = threadIdx.x;
    const int wid  = tid >> 5;
    const int lane = tid & 31;
    const int tg   = lane >> 2;
    const int tk   = lane & 3;
    const int wm   = (wid >> 2) * 64;
    const int wn   = (wid & 3) * 32;

    float acc[4][4][4];
#pragma unroll
    for (int mt = 0; mt < 4; mt++)
#pragma unroll
        for (int nt = 0; nt < 4; nt++)
#pragma unroll
            for (int e = 0; e < 4; e++) acc[mt][nt][e] = 0.0f;

    auto fill = [&](int st, int k0) {
        const uint32_t base = smem_u32(sm + st * SC_STAGE_W);
#pragma unroll
        for (int j = 0; j < 8; j++) {
            const __nv_bfloat16* src = (j < 2) ? Ah : ((j < 4) ? Al : ((j < 6) ? Bh : Bl));
            const int rb  = (j < 4) ? row0 : col0;
            const int pl  = j >> 1;
            const int t   = tid + (j & 1) * 256;
            const int r   = t >> 2;
            const int c16 = t & 3;
            CP_ASYNC16(base + (uint32_t)(pl * SC_PLANE_W + r * SC_ROWW + c16 * 4) * 4u,
                       src + (size_t)(rb + r) * ldk + k0 + c16 * 8);
        }
        CP_COMMIT();
    };

    auto compute = [&](int st) {
        const uint32_t* sAh = sm + st * SC_STAGE_W;
        const uint32_t* sAl = sAh + SC_PLANE_W;
        const uint32_t* sBh = sAl + SC_PLANE_W;
        const uint32_t* sBl = sBh + SC_PLANE_W;
#pragma unroll
        for (int s = 0; s < 2; s++) {
            uint32_t bh[4][2], bl[4][2];
#pragma unroll
            for (int nt = 0; nt < 4; nt++) {
                const int i0 = (wn + nt * 8 + tg) * SC_ROWW + s * 8 + tk;
                bh[nt][0] = sBh[i0]; bh[nt][1] = sBh[i0 + 4];
                bl[nt][0] = sBl[i0]; bl[nt][1] = sBl[i0 + 4];
            }
#pragma unroll
            for (int mt = 0; mt < 4; mt++) {
                const int r0i = (wm + mt * 16 + tg) * SC_ROWW + s * 8 + tk;
                const int r1i = r0i + 8 * SC_ROWW;
                uint32_t ah[4], al[4];
                ah[0] = sAh[r0i];     ah[1] = sAh[r1i];
                ah[2] = sAh[r0i + 4]; ah[3] = sAh[r1i + 4];
                al[0] = sAl[r0i];     al[1] = sAl[r1i];
                al[2] = sAl[r0i + 4]; al[3] = sAl[r1i + 4];
#pragma unroll
                for (int nt = 0; nt < 4; nt++) mma16bf(acc[mt][nt], ah, bh[nt]);
#pragma unroll
                for (int nt = 0; nt < 4; nt++) mma16bf(acc[mt][nt], ah, bl[nt]);
#pragma unroll
                for (int nt = 0; nt < 4; nt++) mma16bf(acc[mt][nt], al, bh[nt]);
            }
        }
    };

    const int nchunk = K / 32;
    fill(0, 0);
    for (int i = 0; i < nchunk; i++) {
        CP_WAIT0();
        __syncthreads();
        if (i + 1 < nchunk) fill((i + 1) & 1, (i + 1) * 32);
        compute(i & 1);
    }

    // epilogue
#pragma unroll
    for (int mt = 0; mt < 4; mt++) {
        const int r = row0 + wm + mt * 16 + tg;
#pragma unroll
        for (int nt = 0; nt < 4; nt++) {
            const int col = col0 + wn + nt * 8 + tk * 2;
            float v[4];
            v[0] = acc[mt][nt][0] * alpha;
            v[1] = acc[mt][nt][1] * alpha;
            v[2] = acc[mt][nt][2] * alpha;
            v[3] = acc[mt][nt][3] * alpha;
            if (HASBIAS) {
                const float b0 = bias[col], b1 = bias[col + 1];
                v[0] += b0; v[1] += b1;
                v[2] += b0; v[3] += b1;
            }
            if (EPI == 3) {
                __nv_bfloat16 h[4], l[4];
#pragma unroll
                for (int e = 0; e < 4; e++) split_bf16(v[e], h[e], l[e]);
                __nv_bfloat162 ph0; ph0.x = h[0]; ph0.y = h[1];
                __nv_bfloat162 pl0; pl0.x = l[0]; pl0.y = l[1];
                __nv_bfloat162 ph1; ph1.x = h[2]; ph1.y = h[3];
                __nv_bfloat162 pl1; pl1.x = l[2]; pl1.y = l[3];
                *(__nv_bfloat162*)(Cbh + (size_t)r * ldc + col)       = ph0;
                *(__nv_bfloat162*)(Cbl + (size_t)r * ldc + col)       = pl0;
                *(__nv_bfloat162*)(Cbh + (size_t)(r + 8) * ldc + col) = ph1;
                *(__nv_bfloat162*)(Cbl + (size_t)(r + 8) * ldc + col) = pl1;
            } else {
                float2 v0, v1;
                if (EPI == 1) {
                    v0 = make_float2(__uint_as_float(to_tf32(v[0])),
                                     __uint_as_float(to_tf32(v[1])));
                    v1 = make_float2(__uint_as_float(to_tf32(v[2])),
                                     __uint_as_float(to_tf32(v[3])));
                } else {
                    v0 = make_float2(v[0], v[1]);
                    v1 = make_float2(v[2], v[3]);
                }
                *(float2*)(C + (size_t)r * ldc + col)       = v0;
                *(float2*)(C + (size_t)(r + 8) * ldc + col) = v1;
            }
        }
    }
}

// ---------------------------------------------------------------------------
// Kernel: all three projections, bf16x3 on pre-split planes.
// grid (8, 64, 3): z=0 Q (bf16-plane out), z=1 K (bf16-plane out),
// z=2 V (tf32-rounded fp32 out)
// ---------------------------------------------------------------------------
__global__ __launch_bounds__(256, 2)
void proj_qkv_k(const __nv_bfloat16* __restrict__ INh,
                const __nv_bfloat16* __restrict__ INl,
                const __nv_bfloat16* __restrict__ Wh,
                const __nv_bfloat16* __restrict__ Wl,
                const float* __restrict__ bq, const float* __restrict__ bk,
                const float* __restrict__ bv,
                __nv_bfloat16* __restrict__ Qh, __nv_bfloat16* __restrict__ Ql,
                __nv_bfloat16* __restrict__ Kh, __nv_bfloat16* __restrict__ Kl,
                float* __restrict__ V)
{
    const int z = blockIdx.z;
    const __nv_bfloat16* Ah = INh + (size_t)z * INELEM;
    const __nv_bfloat16* Al = INl + (size_t)z * INELEM;
    const __nv_bfloat16* Bh = Wh + (size_t)z * WELEM;
    const __nv_bfloat16* Bl = Wl + (size_t)z * WELEM;
    const int row0 = blockIdx.y * 128;
    const int col0 = blockIdx.x * 128;
    if (z == 0)
        bf3_body<3, true>(Ah, Al, Bh, Bl, bq, nullptr, Qh, Ql,
                          DMODEL, DMODEL, DMODEL, 1.0f, row0, col0);
    else if (z == 1)
        bf3_body<3, true>(Ah, Al, Bh, Bl, bk, nullptr, Kh, Kl,
                          DMODEL, DMODEL, DMODEL, 1.0f, row0, col0);
    else
        bf3_body<1, true>(Ah, Al, Bh, Bl, bv, V, nullptr, nullptr,
                          DMODEL, DMODEL, DMODEL, 1.0f, row0, col0);
}

// ---------------------------------------------------------------------------
// Kernel: scores = 8 * Q @ K^T, bf16x3. grid (16, 16, 4)
// ---------------------------------------------------------------------------
__global__ __launch_bounds__(256, 2)
void scores_k(const __nv_bfloat16* __restrict__ Qh,
              const __nv_bfloat16* __restrict__ Ql,
              const __nv_bfloat16* __restrict__ Kh,
              const __nv_bfloat16* __restrict__ Kl,
              float* __restrict__ Sg)
{
    const size_t zo = (size_t)blockIdx.z * SEQ * DMODEL;
    bf3_body<0, false>(Qh + zo, Ql + zo, Kh + zo, Kl + zo, nullptr,
                       Sg + (size_t)blockIdx.z * SEQ * SEQ, nullptr, nullptr,
                       DMODEL, DMODEL, SEQ, 8.0f,
                       blockIdx.y * 128, blockIdx.x * 128);
}

// ===========================================================================
// tf32 GEMM body for PV (operands pre-rounded tf32 bits, conversion-free)
// ===========================================================================
#define A_TILE_F 4608
#define B_TILE_F 4608
#define STAGE_F  (A_TILE_F + B_TILE_F)
#define STAGES   3
#define PV_SMEM_BYTES (STAGES * STAGE_F * 4)   // 110592

__device__ __forceinline__
void pv_body(const float* __restrict__ A, const float* __restrict__ B,
             float* __restrict__ C, int row0, int col0)
{
    extern __shared__ float smem[];
    const int K = SEQ, lda = SEQ, ldb = DMODEL, ldc = DMODEL;

    const int tid  = threadIdx.x;
    const int wid  = tid >> 5;
    const int lane = tid & 31;
    const int tg   = lane >> 2;
    const int tk   = lane & 3;
    const int wm   = (wid >> 2) * 64;
    const int wn   = (wid & 3) * 32;

    float acc[4][4][4];
#pragma unroll
    for (int mt = 0; mt < 4; mt++)
#pragma unroll
        for (int nt = 0; nt < 4; nt++)
#pragma unroll
            for (int e = 0; e < 4; e++) acc[mt][nt][e] = 0.0f;

    auto fill = [&](int st, int k0) {
        float* base = smem + st * STAGE_F;
        const uint32_t sAa = smem_u32(base);
        const uint32_t sBa = smem_u32(base + A_TILE_F);
#pragma unroll
        for (int j = 0; j < 4; j++) {
            const int idx = tid + j * 256;
            const int r  = idx >> 3;
            const int c4 = (idx & 7) << 2;
            CP_ASYNC16(sAa + (uint32_t)(r * 36 + c4) * 4u,
                       A + (size_t)(row0 + r) * lda + k0 + c4);
        }
#pragma unroll
        for (int j = 0; j < 4; j++) {
            const int idx = tid + j * 256;
            const int kk = idx >> 5;
            const int n4 = (idx & 31) << 2;
            CP_ASYNC16(sBa + (uint32_t)(kk * 136 + n4) * 4u,
                       B + (size_t)(k0 + kk) * ldb + col0 + n4);
        }
        CP_COMMIT();
    };

    auto compute = [&](int st) {
        const uint32_t* uA = (const uint32_t*)(smem + st * STAGE_F);
        const uint32_t* uB = uA + A_TILE_F;
#pragma unroll
        for (int s = 0; s < 4; s++) {
            uint32_t bh[4][2];
#pragma unroll
            for (int nt = 0; nt < 4; nt++) {
                const int n0 = wn + nt * 8;
                bh[nt][0] = uB[(s * 8 + tk)     * 136 + n0 + tg];
                bh[nt][1] = uB[(s * 8 + tk + 4) * 136 + n0 + tg];
            }
#pragma unroll
            for (int mt = 0; mt < 4; mt++) {
                const int m0 = wm + mt * 16;
                const int i0 = (m0 + tg) * 36 + s * 8 + tk;
                const int i1 = i0 + 8 * 36;
                uint32_t at[4];
                at[0] = uA[i0];
                at[1] = uA[i1];
                at[2] = uA[i0 + 4];
                at[3] = uA[i1 + 4];
#pragma unroll
                for (int nt = 0; nt < 4; nt++) mma8(acc[mt][nt], at, bh[nt]);
            }
        }
    };

    const int nchunk = K >> 5;
    fill(0, 0);
    fill(1, 32);
    for (int i = 0; i < nchunk; i++) {
        if (i + 1 < nchunk) { CP_WAIT1(); }
        else                { CP_WAIT0(); }
        __syncthreads();
        if (i + 2 < nchunk) fill((i + 2) % STAGES, (i + 2) << 5);
        compute(i % STAGES);
    }

#pragma unroll
    for (int mt = 0; mt < 4; mt++) {
        const int r = row0 + wm + mt * 16 + tg;
#pragma unroll
        for (int nt = 0; nt < 4; nt++) {
            const int col = col0 + wn + nt * 8 + tk * 2;
            *(float2*)(C + (size_t)r * ldc + col) =
                make_float2(acc[mt][nt][0], acc[mt][nt][1]);
            *(float2*)(C + (size_t)(r + 8) * ldc + col) =
                make_float2(acc[mt][nt][2], acc[mt][nt][3]);
        }
    }
}

__global__ __launch_bounds__(256, 2)
void pv_k(const float* __restrict__ Pg, const float* __restrict__ Vt,
          float* __restrict__ Og)
{
    const size_t z = blockIdx.z;
    pv_body(Pg + z * SEQ * SEQ, Vt + z * SEQ * DMODEL, Og + z * SEQ * DMODEL,
            blockIdx.y * 128, blockIdx.x * 128);
}

// ---------------------------------------------------------------------------
// JAX threefry2x32, key (0,42), partitionable scheme
// ---------------------------------------------------------------------------
__device__ __forceinline__ uint32_t threefry_mask_word(uint32_t idx)
{
    const uint32_t ks0 = 0u;
    const uint32_t ks1 = 42u;
    const uint32_t ks2 = 42u ^ 0x1BD11BDAu;
    uint32_t x0 = ks0;
    uint32_t x1 = idx + ks1;
#define TFR(r) { x0 += x1; x1 = __funnelshift_l(x1, x1, (r)); x1 ^= x0; }
    TFR(13) TFR(15) TFR(26) TFR(6)
    x0 += ks1; x1 += ks2 + 1u;
    TFR(17) TFR(29) TFR(16) TFR(24)
    x0 += ks2; x1 += ks0 + 2u;
    TFR(13) TFR(15) TFR(26) TFR(6)
    x0 += ks0; x1 += ks1 + 3u;
    TFR(17) TFR(29) TFR(16) TFR(24)
    x0 += ks1; x1 += ks2 + 4u;
    TFR(13) TFR(15) TFR(26) TFR(6)
    x0 += ks2; x1 += ks0 + 5u;
#undef TFR
    return x0 ^ x1;
}

// ---------------------------------------------------------------------------
// Softmax + dropout; P written pre-rounded tf32 (PV is conversion-free)
// ---------------------------------------------------------------------------
__global__ __launch_bounds__(256, 4)
void softmax_dropout_k(float* __restrict__ S)
{
    const int q   = blockIdx.x;
    const int b   = blockIdx.y;
    const int tid = threadIdx.x;
    float* __restrict__ row = S + ((size_t)b * SEQ + q) * SEQ;

    float a[8];
#pragma unroll
    for (int j = 0; j < 8; j++) a[j] = row[tid + j * 256];

    float m = a[0];
#pragma unroll
    for (int j = 1; j < 8; j++) m = fmaxf(m, a[j]);
#pragma unroll
    for (int s = 16; s > 0; s >>= 1)
        m = fmaxf(m, __shfl_xor_sync(0xffffffffu, m, s));
    __shared__ float red[8];
    const int wid = tid >> 5, lane = tid & 31;
    if (lane == 0) red[wid] = m;
    __syncthreads();
    m = red[0];
#pragma unroll
    for (int w = 1; w < 8; w++) m = fmaxf(m, red[w]);
    __syncthreads();

    float s0 = 0.0f;
#pragma unroll
    for (int j = 0; j < 8; j++) {
        a[j] = __expf(a[j] - m);
        s0 += a[j];
    }
#pragma unroll
    for (int s = 16; s > 0; s >>= 1)
        s0 += __shfl_xor_sync(0xffffffffu, s0, s);
    if (lane == 0) red[wid] = s0;
    __syncthreads();
    s0 = 0.0f;
#pragma unroll
    for (int w = 0; w < 8; w++) s0 += red[w];

    const float inv = 2.0f / s0;

    const uint32_t base = ((uint32_t)(b * SEQ + q)) * (uint32_t)SEQ;
#pragma unroll
    for (int j = 0; j < 8; j++) {
        const uint32_t k = (uint32_t)tid + (uint32_t)j * 256u;
        const uint32_t w = threefry_mask_word(base + k);
        const float val = (w >> 31) ? 0.0f : a[j] * inv;
        row[k] = __uint_as_float(to_tf32(val));
    }
}

// ---------------------------------------------------------------------------
// Launcher
// ---------------------------------------------------------------------------
extern "C" void kernel_launch(void* const* d_in, const int* in_sizes, int n_in,
                              void* d_out, int out_size)
{
    (void)in_sizes; (void)n_in; (void)out_size;
    const float* query = (const float*)d_in[0];
    const float* key_  = (const float*)d_in[1];
    const float* value = (const float*)d_in[2];
    const float* Wq    = (const float*)d_in[3];
    const float* bq    = (const float*)d_in[4];
    const float* Wk    = (const float*)d_in[5];
    const float* bk    = (const float*)d_in[6];
    const float* Wv    = (const float*)d_in[7];
    const float* bv    = (const float*)d_in[8];
    float* out = (float*)d_out;

    __nv_bfloat16 *dINh, *dINl, *dWh, *dWl, *dQh, *dQl, *dKh, *dKl;
    float *dV, *dS;
    cudaGetSymbolAddress((void**)&dINh, g_INh);
    cudaGetSymbolAddress((void**)&dINl, g_INl);
    cudaGetSymbolAddress((void**)&dWh,  g_Wh);
    cudaGetSymbolAddress((void**)&dWl,  g_Wl);
    cudaGetSymbolAddress((void**)&dQh,  g_Qh);
    cudaGetSymbolAddress((void**)&dQl,  g_Ql);
    cudaGetSymbolAddress((void**)&dKh,  g_Kh);
    cudaGetSymbolAddress((void**)&dKl,  g_Kl);
    cudaGetSymbolAddress((void**)&dV,   g_V);
    cudaGetSymbolAddress((void**)&dS,   g_S);

    static bool attr_done = false;
    if (!attr_done) {
        cudaFuncSetAttribute(proj_qkv_k,
                             cudaFuncAttributeMaxDynamicSharedMemorySize, BF3_SMEM_BYTES);
        cudaFuncSetAttribute(scores_k,
                             cudaFuncAttributeMaxDynamicSharedMemorySize, BF3_SMEM_BYTES);
        cudaFuncSetAttribute(pv_k,
                             cudaFuncAttributeMaxDynamicSharedMemorySize, PV_SMEM_BYTES);
        attr_done = true;
    }

    dim3 thr(256);

    // 0a) split inputs -> bf16 planes
    dim3 gSI(INELEM / (256 * 4), 1, 3);
    split_in_k<<<gSI, thr>>>(query, key_, value, dINh, dINl);

    // 0b) transpose + split W -> K-major bf16 planes
    dim3 gSW(DMODEL / 32, DMODEL / 32, 3);
    split_w_k<<<gSW, dim3(32, 8)>>>(Wq, Wk, Wv, dWh, dWl);

    // 1) Projections Q,K,V — bf16x3, conversion-free
    dim3 gP(DMODEL / 128, (BATCH * SEQ) / 128, 3);
    proj_qkv_k<<<gP, thr, BF3_SMEM_BYTES>>>(dINh, dINl, dWh, dWl,
                                            bq, bk, bv,
                                            dQh, dQl, dKh, dKl, dV);

    // 2) Scores — bf16x3
    dim3 gS(SEQ / 128, SEQ / 128, BATCH);
    scores_k<<<gS, thr, BF3_SMEM_BYTES>>>(dQh, dQl, dKh, dKl, dS);

    // 3) Softmax + threefry dropout; P pre-rounded tf32
    dim3 gSm(SEQ, BATCH, 1);
    softmax_dropout_k<<<gSm, thr>>>(dS);

    // 4) O = P @ Vt (conversion-free tf32 x1)
    dim3 gO(DMODEL / 128, SEQ / 128, BATCH);
    pv_k<<<gO, thr, PV_SMEM_BYTES>>>(dS, dV, out);
}

// round 14
// speedup vs baseline: 1.7341x; 1.0830x over previous
#include <cuda_runtime.h>
#include <cuda_bf16.h>
#include <cstdint>

// ---------------------------------------------------------------------------
// Problem constants
// ---------------------------------------------------------------------------
#define BATCH  4
#define SEQ    2048
#define DMODEL 1024
#define INELEM ((size_t)BATCH * SEQ * DMODEL)   // 8388608
#define WELEM  ((size_t)DMODEL * DMODEL)        // 1048576

// Scratch (device globals: allocation-free)
__device__ __nv_bfloat16 g_INh[3 * INELEM];
__device__ __nv_bfloat16 g_INl[3 * INELEM];
__device__ __nv_bfloat16 g_Wh[3 * WELEM];   // transposed W planes [n][k]
__device__ __nv_bfloat16 g_Wl[3 * WELEM];
__device__ __nv_bfloat16 g_Qh[INELEM];
__device__ __nv_bfloat16 g_Ql[INELEM];
__device__ __nv_bfloat16 g_Kh[INELEM];
__device__ __nv_bfloat16 g_Kl[INELEM];
__device__ float g_V[INELEM];                      // pre-rounded tf32 bits
__device__ float g_S[(size_t)BATCH * SEQ * SEQ];   // scores, then tf32 P

// ---------------------------------------------------------------------------
// Helpers
// ---------------------------------------------------------------------------
__device__ __forceinline__ uint32_t smem_u32(const void* p) {
    uint32_t a;
    asm("{ .reg .u64 t; cvta.to.shared.u64 t, %1; cvt.u32.u64 %0, t; }"
        : "=r"(a) : "l"(p));
    return a;
}

#define CP_ASYNC16(saddr, gptr) \
    asm volatile("cp.async.cg.shared.global [%0], [%1], 16;" \
        :: "r"(saddr), "l"(gptr) : "memory")
#define CP_COMMIT() asm volatile("cp.async.commit_group;" ::: "memory")
#define CP_WAIT0()  asm volatile("cp.async.wait_group 0;" ::: "memory")
#define CP_WAIT1()  asm volatile("cp.async.wait_group 1;" ::: "memory")

#define LDSM_X4(r0, r1, r2, r3, addr) \
    asm volatile("ldmatrix.sync.aligned.m8n8.x4.shared.b16 {%0,%1,%2,%3}, [%4];" \
        : "=r"(r0), "=r"(r1), "=r"(r2), "=r"(r3) : "r"(addr))

__device__ __forceinline__ uint32_t to_tf32(float x) {
    uint32_t t;
    asm("cvt.rna.tf32.f32 %0, %1;" : "=r"(t) : "f"(x));
    return t;
}

__device__ __forceinline__ void split_bf16(float x, __nv_bfloat16& h, __nv_bfloat16& l) {
    h = __float2bfloat16_rn(x);
    l = __float2bfloat16_rn(x - __bfloat162float(h));
}

// D += A(16x8 tf32) * B(8x8 tf32), fp32 accumulate
__device__ __forceinline__ void mma8(float* d, const uint32_t* a, const uint32_t* b) {
    asm volatile(
        "mma.sync.aligned.m16n8k8.row.col.f32.tf32.tf32.f32 "
        "{%0,%1,%2,%3}, {%4,%5,%6,%7}, {%8,%9}, {%0,%1,%2,%3};"
        : "+f"(d[0]), "+f"(d[1]), "+f"(d[2]), "+f"(d[3])
        : "r"(a[0]), "r"(a[1]), "r"(a[2]), "r"(a[3]), "r"(b[0]), "r"(b[1]));
}

// D += A(16x16 bf16) * B(16x8 bf16), fp32 accumulate
__device__ __forceinline__ void mma16bf(float* d, const uint32_t* a, const uint32_t* b) {
    asm volatile(
        "mma.sync.aligned.m16n8k16.row.col.f32.bf16.bf16.f32 "
        "{%0,%1,%2,%3}, {%4,%5,%6,%7}, {%8,%9}, {%0,%1,%2,%3};"
        : "+f"(d[0]), "+f"(d[1]), "+f"(d[2]), "+f"(d[3])
        : "r"(a[0]), "r"(a[1]), "r"(a[2]), "r"(a[3]), "r"(b[0]), "r"(b[1]));
}

// ===========================================================================
// Pre-pass 1: split query/key/value (fp32) -> bf16 hi/lo planes
// ===========================================================================
__global__ __launch_bounds__(256)
void split_in_k(const float* __restrict__ q, const float* __restrict__ k,
                const float* __restrict__ v,
                __nv_bfloat16* __restrict__ oh, __nv_bfloat16* __restrict__ ol)
{
    const float* src = (blockIdx.z == 0) ? q : ((blockIdx.z == 1) ? k : v);
    const size_t base = (size_t)blockIdx.z * INELEM;
    const size_t i = ((size_t)blockIdx.x * 256 + threadIdx.x) * 4;
    float4 x = *(const float4*)(src + i);
    __nv_bfloat16 h0, h1, h2, h3, l0, l1, l2, l3;
    split_bf16(x.x, h0, l0);
    split_bf16(x.y, h1, l1);
    split_bf16(x.z, h2, l2);
    split_bf16(x.w, h3, l3);
    __nv_bfloat162 ph0; ph0.x = h0; ph0.y = h1;
    __nv_bfloat162 ph1; ph1.x = h2; ph1.y = h3;
    __nv_bfloat162 pl0; pl0.x = l0; pl0.y = l1;
    __nv_bfloat162 pl1; pl1.x = l2; pl1.y = l3;
    *(__nv_bfloat162*)(oh + base + i)     = ph0;
    *(__nv_bfloat162*)(oh + base + i + 2) = ph1;
    *(__nv_bfloat162*)(ol + base + i)     = pl0;
    *(__nv_bfloat162*)(ol + base + i + 2) = pl1;
}

// ===========================================================================
// Pre-pass 2: transpose + split W[k][n] -> Wt planes [n][k]
// ===========================================================================
__global__ __launch_bounds__(256)
void split_w_k(const float* __restrict__ Wq, const float* __restrict__ Wk,
               const float* __restrict__ Wv,
               __nv_bfloat16* __restrict__ oh, __nv_bfloat16* __restrict__ ol)
{
    const float* W = (blockIdx.z == 0) ? Wq : ((blockIdx.z == 1) ? Wk : Wv);
    const size_t base = (size_t)blockIdx.z * WELEM;
    __shared__ float t[32][33];
    const int kb = blockIdx.y * 32;
    const int nb = blockIdx.x * 32;
    const int tx = threadIdx.x, ty = threadIdx.y;
#pragma unroll
    for (int j = 0; j < 4; j++)
        t[ty + 8 * j][tx] = W[(size_t)(kb + ty + 8 * j) * DMODEL + nb + tx];
    __syncthreads();
#pragma unroll
    for (int j = 0; j < 4; j++) {
        const float val = t[tx][ty + 8 * j];
        __nv_bfloat16 h, l;
        split_bf16(val, h, l);
        const size_t o = base + (size_t)(nb + ty + 8 * j) * DMODEL + kb + tx;
        oh[o] = h;
        ol[o] = l;
    }
}

// ===========================================================================
// bf16x3 GEMM body with ldmatrix fragment loads.
// A planes [Mrows, K] k-contig (row0), B planes [Nrows, K] k-contig (col0).
// KC=32 (2 k16-steps), 2-stage, 256 thr, 8 warps 64x32.
// Rows padded to 20 words (80B): ldmatrix 8-row phases are bank-conflict-free
// (20r mod 32 cycles 8 distinct 4-bank ranges).
//   EPI=0: fp32*alpha   EPI=1: +bias, rna-tf32 out   EPI=3: +bias, bf16 planes
// ===========================================================================
#define SC_ROWW    20
#define SC_PLANE_W (128 * SC_ROWW)       // 2560 words
#define SC_STAGE_W (4 * SC_PLANE_W)      // 10240 words
#define BF3_SMEM_BYTES (2 * SC_STAGE_W * 4)   // 81920

template <int EPI, bool HASBIAS>
__device__ __forceinline__
void bf3_body(const __nv_bfloat16* __restrict__ Ah,
              const __nv_bfloat16* __restrict__ Al,
              const __nv_bfloat16* __restrict__ Bh,
              const __nv_bfloat16* __restrict__ Bl,
              const float* __restrict__ bias,
              float* __restrict__ C,
              __nv_bfloat16* __restrict__ Cbh, __nv_bfloat16* __restrict__ Cbl,
              int K, int ldk, int ldc, float alpha, int row0, int col0)
{
    extern __shared__ float smemf[];
    uint32_t* sm = (uint32_t*)smemf;

    const int tid  = threadIdx.x;
    const int wid  = tid >> 5;
    const int lane = tid & 31;
    const int tg   = lane >> 2;
    const int tk   = lane & 3;
    const int wm   = (wid >> 2) * 64;
    const int wn   = (wid & 3) * 32;

    // ldmatrix lane address offsets (in words, within a plane)
    // A x4: lanes 0-7 -> m0 rows (tile rows 0-7, k-words +0)  -> a0
    //       lanes 8-15 -> rows 8-15 +0 -> a1 ; 16-23 -> rows 0-7 +4 -> a2 ;
    //       24-31 -> rows 8-15 +4 -> a3
    const uint32_t aOffW = (uint32_t)((wm + (lane & 15)) * SC_ROWW + (lane >> 4) * 4);
    // B x4 (nt pair p): lanes 0-7 -> n rows 0-7 +0 (b[2p][0]) ; 8-15 -> rows 0-7 +4
    //       (b[2p][1]) ; 16-23 -> rows 8-15 +0 (b[2p+1][0]) ; 24-31 -> rows 8-15 +4
    const uint32_t bOffW = (uint32_t)((wn + (lane & 7) + (lane >> 4) * 8) * SC_ROWW
                                      + ((lane >> 3) & 1) * 4);

    float acc[4][4][4];
#pragma unroll
    for (int mt = 0; mt < 4; mt++)
#pragma unroll
        for (int nt = 0; nt < 4; nt++)
#pragma unroll
            for (int e = 0; e < 4; e++) acc[mt][nt][e] = 0.0f;

    auto fill = [&](int st, int k0) {
        const uint32_t base = smem_u32(sm + st * SC_STAGE_W);
#pragma unroll
        for (int j = 0; j < 8; j++) {
            const __nv_bfloat16* src = (j < 2) ? Ah : ((j < 4) ? Al : ((j < 6) ? Bh : Bl));
            const int rb  = (j < 4) ? row0 : col0;
            const int pl  = j >> 1;
            const int t   = tid + (j & 1) * 256;
            const int r   = t >> 2;
            const int c16 = t & 3;
            CP_ASYNC16(base + (uint32_t)(pl * SC_PLANE_W + r * SC_ROWW + c16 * 4) * 4u,
                       src + (size_t)(rb + r) * ldk + k0 + c16 * 8);
        }
        CP_COMMIT();
    };

    auto compute = [&](int st) {
        const uint32_t stb = smem_u32(sm + st * SC_STAGE_W);
        const uint32_t adAh = stb + aOffW * 4u;
        const uint32_t adAl = adAh + SC_PLANE_W * 4u;
        const uint32_t adBh = stb + 2u * SC_PLANE_W * 4u + bOffW * 4u;
        const uint32_t adBl = adBh + SC_PLANE_W * 4u;
#pragma unroll
        for (int s = 0; s < 2; s++) {
            const uint32_t so = (uint32_t)(s * 8) * 4u;
            uint32_t bh[4][2], bl[4][2];
#pragma unroll
            for (int p = 0; p < 2; p++) {
                const uint32_t po = (uint32_t)(p * 16 * SC_ROWW) * 4u;
                LDSM_X4(bh[2 * p][0], bh[2 * p][1], bh[2 * p + 1][0], bh[2 * p + 1][1],
                        adBh + po + so);
                LDSM_X4(bl[2 * p][0], bl[2 * p][1], bl[2 * p + 1][0], bl[2 * p + 1][1],
                        adBl + po + so);
            }
#pragma unroll
            for (int mt = 0; mt < 4; mt++) {
                const uint32_t mo = (uint32_t)(mt * 16 * SC_ROWW) * 4u;
                uint32_t ah[4], al[4];
                LDSM_X4(ah[0], ah[1], ah[2], ah[3], adAh + mo + so);
                LDSM_X4(al[0], al[1], al[2], al[3], adAl + mo + so);
#pragma unroll
                for (int nt = 0; nt < 4; nt++) mma16bf(acc[mt][nt], ah, bh[nt]);
#pragma unroll
                for (int nt = 0; nt < 4; nt++) mma16bf(acc[mt][nt], ah, bl[nt]);
#pragma unroll
                for (int nt = 0; nt < 4; nt++) mma16bf(acc[mt][nt], al, bh[nt]);
            }
        }
    };

    const int nchunk = K / 32;
    fill(0, 0);
    for (int i = 0; i < nchunk; i++) {
        CP_WAIT0();
        __syncthreads();
        if (i + 1 < nchunk) fill((i + 1) & 1, (i + 1) * 32);
        compute(i & 1);
    }

    // epilogue
#pragma unroll
    for (int mt = 0; mt < 4; mt++) {
        const int r = row0 + wm + mt * 16 + tg;
#pragma unroll
        for (int nt = 0; nt < 4; nt++) {
            const int col = col0 + wn + nt * 8 + tk * 2;
            float v[4];
            v[0] = acc[mt][nt][0] * alpha;
            v[1] = acc[mt][nt][1] * alpha;
            v[2] = acc[mt][nt][2] * alpha;
            v[3] = acc[mt][nt][3] * alpha;
            if (HASBIAS) {
                const float b0 = bias[col], b1 = bias[col + 1];
                v[0] += b0; v[1] += b1;
                v[2] += b0; v[3] += b1;
            }
            if (EPI == 3) {
                __nv_bfloat16 h[4], l[4];
#pragma unroll
                for (int e = 0; e < 4; e++) split_bf16(v[e], h[e], l[e]);
                __nv_bfloat162 ph0; ph0.x = h[0]; ph0.y = h[1];
                __nv_bfloat162 pl0; pl0.x = l[0]; pl0.y = l[1];
                __nv_bfloat162 ph1; ph1.x = h[2]; ph1.y = h[3];
                __nv_bfloat162 pl1; pl1.x = l[2]; pl1.y = l[3];
                *(__nv_bfloat162*)(Cbh + (size_t)r * ldc + col)       = ph0;
                *(__nv_bfloat162*)(Cbl + (size_t)r * ldc + col)       = pl0;
                *(__nv_bfloat162*)(Cbh + (size_t)(r + 8) * ldc + col) = ph1;
                *(__nv_bfloat162*)(Cbl + (size_t)(r + 8) * ldc + col) = pl1;
            } else {
                float2 v0, v1;
                if (EPI == 1) {
                    v0 = make_float2(__uint_as_float(to_tf32(v[0])),
                                     __uint_as_float(to_tf32(v[1])));
                    v1 = make_float2(__uint_as_float(to_tf32(v[2])),
                                     __uint_as_float(to_tf32(v[3])));
                } else {
                    v0 = make_float2(v[0], v[1]);
                    v1 = make_float2(v[2], v[3]);
                }
                *(float2*)(C + (size_t)r * ldc + col)       = v0;
                *(float2*)(C + (size_t)(r + 8) * ldc + col) = v1;
            }
        }
    }
}

// ---------------------------------------------------------------------------
// Projections: bf16x3 + ldmatrix. grid (8, 64, 3)
// ---------------------------------------------------------------------------
__global__ __launch_bounds__(256, 2)
void proj_qkv_k(const __nv_bfloat16* __restrict__ INh,
                const __nv_bfloat16* __restrict__ INl,
                const __nv_bfloat16* __restrict__ Wh,
                const __nv_bfloat16* __restrict__ Wl,
                const float* __restrict__ bq, const float* __restrict__ bk,
                const float* __restrict__ bv,
                __nv_bfloat16* __restrict__ Qh, __nv_bfloat16* __restrict__ Ql,
                __nv_bfloat16* __restrict__ Kh, __nv_bfloat16* __restrict__ Kl,
                float* __restrict__ V)
{
    const int z = blockIdx.z;
    const __nv_bfloat16* Ah = INh + (size_t)z * INELEM;
    const __nv_bfloat16* Al = INl + (size_t)z * INELEM;
    const __nv_bfloat16* Bh = Wh + (size_t)z * WELEM;
    const __nv_bfloat16* Bl = Wl + (size_t)z * WELEM;
    const int row0 = blockIdx.y * 128;
    const int col0 = blockIdx.x * 128;
    if (z == 0)
        bf3_body<3, true>(Ah, Al, Bh, Bl, bq, nullptr, Qh, Ql,
                          DMODEL, DMODEL, DMODEL, 1.0f, row0, col0);
    else if (z == 1)
        bf3_body<3, true>(Ah, Al, Bh, Bl, bk, nullptr, Kh, Kl,
                          DMODEL, DMODEL, DMODEL, 1.0f, row0, col0);
    else
        bf3_body<1, true>(Ah, Al, Bh, Bl, bv, V, nullptr, nullptr,
                          DMODEL, DMODEL, DMODEL, 1.0f, row0, col0);
}

// ---------------------------------------------------------------------------
// Scores: bf16x3 + ldmatrix. grid (16, 16, 4)
// ---------------------------------------------------------------------------
__global__ __launch_bounds__(256, 2)
void scores_k(const __nv_bfloat16* __restrict__ Qh,
              const __nv_bfloat16* __restrict__ Ql,
              const __nv_bfloat16* __restrict__ Kh,
              const __nv_bfloat16* __restrict__ Kl,
              float* __restrict__ Sg)
{
    const size_t zo = (size_t)blockIdx.z * SEQ * DMODEL;
    bf3_body<0, false>(Qh + zo, Ql + zo, Kh + zo, Kl + zo, nullptr,
                       Sg + (size_t)blockIdx.z * SEQ * SEQ, nullptr, nullptr,
                       DMODEL, DMODEL, SEQ, 8.0f,
                       blockIdx.y * 128, blockIdx.x * 128);
}

// ===========================================================================
// PV body: tf32 x1, operands pre-rounded (conversion-free)
// ===========================================================================
#define A_TILE_F 4608
#define B_TILE_F 4608
#define STAGE_F  (A_TILE_F + B_TILE_F)
#define STAGES   3
#define PV_SMEM_BYTES (STAGES * STAGE_F * 4)

__device__ __forceinline__
void pv_body(const float* __restrict__ A, const float* __restrict__ B,
             float* __restrict__ C, int row0, int col0)
{
    extern __shared__ float smem[];
    const int K = SEQ, lda = SEQ, ldb = DMODEL, ldc = DMODEL;

    const int tid  = threadIdx.x;
    const int wid  = tid >> 5;
    const int lane = tid & 31;
    const int tg   = lane >> 2;
    const int tk   = lane & 3;
    const int wm   = (wid >> 2) * 64;
    const int wn   = (wid & 3) * 32;

    float acc[4][4][4];
#pragma unroll
    for (int mt = 0; mt < 4; mt++)
#pragma unroll
        for (int nt = 0; nt < 4; nt++)
#pragma unroll
            for (int e = 0; e < 4; e++) acc[mt][nt][e] = 0.0f;

    auto fill = [&](int st, int k0) {
        float* base = smem + st * STAGE_F;
        const uint32_t sAa = smem_u32(base);
        const uint32_t sBa = smem_u32(base + A_TILE_F);
#pragma unroll
        for (int j = 0; j < 4; j++) {
            const int idx = tid + j * 256;
            const int r  = idx >> 3;
            const int c4 = (idx & 7) << 2;
            CP_ASYNC16(sAa + (uint32_t)(r * 36 + c4) * 4u,
                       A + (size_t)(row0 + r) * lda + k0 + c4);
        }
#pragma unroll
        for (int j = 0; j < 4; j++) {
            const int idx = tid + j * 256;
            const int kk = idx >> 5;
            const int n4 = (idx & 31) << 2;
            CP_ASYNC16(sBa + (uint32_t)(kk * 136 + n4) * 4u,
                       B + (size_t)(k0 + kk) * ldb + col0 + n4);
        }
        CP_COMMIT();
    };

    auto compute = [&](int st) {
        const uint32_t* uA = (const uint32_t*)(smem + st * STAGE_F);
        const uint32_t* uB = uA + A_TILE_F;
#pragma unroll
        for (int s = 0; s < 4; s++) {
            uint32_t bh[4][2];
#pragma unroll
            for (int nt = 0; nt < 4; nt++) {
                const int n0 = wn + nt * 8;
                bh[nt][0] = uB[(s * 8 + tk)     * 136 + n0 + tg];
                bh[nt][1] = uB[(s * 8 + tk + 4) * 136 + n0 + tg];
            }
#pragma unroll
            for (int mt = 0; mt < 4; mt++) {
                const int m0 = wm + mt * 16;
                const int i0 = (m0 + tg) * 36 + s * 8 + tk;
                const int i1 = i0 + 8 * 36;
                uint32_t at[4];
                at[0] = uA[i0];
                at[1] = uA[i1];
                at[2] = uA[i0 + 4];
                at[3] = uA[i1 + 4];
#pragma unroll
                for (int nt = 0; nt < 4; nt++) mma8(acc[mt][nt], at, bh[nt]);
            }
        }
    };

    const int nchunk = K >> 5;
    fill(0, 0);
    fill(1, 32);
    for (int i = 0; i < nchunk; i++) {
        if (i + 1 < nchunk) { CP_WAIT1(); }
        else                { CP_WAIT0(); }
        __syncthreads();
        if (i + 2 < nchunk) fill((i + 2) % STAGES, (i + 2) << 5);
        compute(i % STAGES);
    }

#pragma unroll
    for (int mt = 0; mt < 4; mt++) {
        const int r = row0 + wm + mt * 16 + tg;
#pragma unroll
        for (int nt = 0; nt < 4; nt++) {
            const int col = col0 + wn + nt * 8 + tk * 2;
            *(float2*)(C + (size_t)r * ldc + col) =
                make_float2(acc[mt][nt][0], acc[mt][nt][1]);
            *(float2*)(C + (size_t)(r + 8) * ldc + col) =
                make_float2(acc[mt][nt][2], acc[mt][nt][3]);
        }
    }
}

__global__ __launch_bounds__(256, 2)
void pv_k(const float* __restrict__ Pg, const float* __restrict__ Vt,
          float* __restrict__ Og)
{
    const size_t z = blockIdx.z;
    pv_body(Pg + z * SEQ * SEQ, Vt + z * SEQ * DMODEL, Og + z * SEQ * DMODEL,
            blockIdx.y * 128, blockIdx.x * 128);
}

// ---------------------------------------------------------------------------
// JAX threefry2x32, key (0,42), partitionable scheme
// ---------------------------------------------------------------------------
__device__ __forceinline__ uint32_t threefry_mask_word(uint32_t idx)
{
    const uint32_t ks0 = 0u;
    const uint32_t ks1 = 42u;
    const uint32_t ks2 = 42u ^ 0x1BD11BDAu;
    uint32_t x0 = ks0;
    uint32_t x1 = idx + ks1;
#define TFR(r) { x0 += x1; x1 = __funnelshift_l(x1, x1, (r)); x1 ^= x0; }
    TFR(13) TFR(15) TFR(26) TFR(6)
    x0 += ks1; x1 += ks2 + 1u;
    TFR(17) TFR(29) TFR(16) TFR(24)
    x0 += ks2; x1 += ks0 + 2u;
    TFR(13) TFR(15) TFR(26) TFR(6)
    x0 += ks0; x1 += ks1 + 3u;
    TFR(17) TFR(29) TFR(16) TFR(24)
    x0 += ks1; x1 += ks2 + 4u;
    TFR(13) TFR(15) TFR(26) TFR(6)
    x0 += ks2; x1 += ks0 + 5u;
#undef TFR
    return x0 ^ x1;
}

// ---------------------------------------------------------------------------
// Softmax + dropout; P written pre-rounded tf32
// ---------------------------------------------------------------------------
__global__ __launch_bounds__(256, 4)
void softmax_dropout_k(float* __restrict__ S)
{
    const int q   = blockIdx.x;
    const int b   = blockIdx.y;
    const int tid = threadIdx.x;
    float* __restrict__ row = S + ((size_t)b * SEQ + q) * SEQ;

    float a[8];
#pragma unroll
    for (int j = 0; j < 8; j++) a[j] = row[tid + j * 256];

    float m = a[0];
#pragma unroll
    for (int j = 1; j < 8; j++) m = fmaxf(m, a[j]);
#pragma unroll
    for (int s = 16; s > 0; s >>= 1)
        m = fmaxf(m, __shfl_xor_sync(0xffffffffu, m, s));
    __shared__ float red[8];
    const int wid = tid >> 5, lane = tid & 31;
    if (lane == 0) red[wid] = m;
    __syncthreads();
    m = red[0];
#pragma unroll
    for (int w = 1; w < 8; w++) m = fmaxf(m, red[w]);
    __syncthreads();

    float s0 = 0.0f;
#pragma unroll
    for (int j = 0; j < 8; j++) {
        a[j] = __expf(a[j] - m);
        s0 += a[j];
    }
#pragma unroll
    for (int s = 16; s > 0; s >>= 1)
        s0 += __shfl_xor_sync(0xffffffffu, s0, s);
    if (lane == 0) red[wid] = s0;
    __syncthreads();
    s0 = 0.0f;
#pragma unroll
    for (int w = 0; w < 8; w++) s0 += red[w];

    const float inv = 2.0f / s0;

    const uint32_t base = ((uint32_t)(b * SEQ + q)) * (uint32_t)SEQ;
#pragma unroll
    for (int j = 0; j < 8; j++) {
        const uint32_t k = (uint32_t)tid + (uint32_t)j * 256u;
        const uint32_t w = threefry_mask_word(base + k);
        const float val = (w >> 31) ? 0.0f : a[j] * inv;
        row[k] = __uint_as_float(to_tf32(val));
    }
}

// ---------------------------------------------------------------------------
// Launcher
// ---------------------------------------------------------------------------
extern "C" void kernel_launch(void* const* d_in, const int* in_sizes, int n_in,
                              void* d_out, int out_size)
{
    (void)in_sizes; (void)n_in; (void)out_size;
    const float* query = (const float*)d_in[0];
    const float* key_  = (const float*)d_in[1];
    const float* value = (const float*)d_in[2];
    const float* Wq    = (const float*)d_in[3];
    const float* bq    = (const float*)d_in[4];
    const float* Wk    = (const float*)d_in[5];
    const float* bk    = (const float*)d_in[6];
    const float* Wv    = (const float*)d_in[7];
    const float* bv    = (const float*)d_in[8];
    float* out = (float*)d_out;

    __nv_bfloat16 *dINh, *dINl, *dWh, *dWl, *dQh, *dQl, *dKh, *dKl;
    float *dV, *dS;
    cudaGetSymbolAddress((void**)&dINh, g_INh);
    cudaGetSymbolAddress((void**)&dINl, g_INl);
    cudaGetSymbolAddress((void**)&dWh,  g_Wh);
    cudaGetSymbolAddress((void**)&dWl,  g_Wl);
    cudaGetSymbolAddress((void**)&dQh,  g_Qh);
    cudaGetSymbolAddress((void**)&dQl,  g_Ql);
    cudaGetSymbolAddress((void**)&dKh,  g_Kh);
    cudaGetSymbolAddress((void**)&dKl,  g_Kl);
    cudaGetSymbolAddress((void**)&dV,   g_V);
    cudaGetSymbolAddress((void**)&dS,   g_S);

    static bool attr_done = false;
    if (!attr_done) {
        cudaFuncSetAttribute(proj_qkv_k,
                             cudaFuncAttributeMaxDynamicSharedMemorySize, BF3_SMEM_BYTES);
        cudaFuncSetAttribute(scores_k,
                             cudaFuncAttributeMaxDynamicSharedMemorySize, BF3_SMEM_BYTES);
        cudaFuncSetAttribute(pv_k,
                             cudaFuncAttributeMaxDynamicSharedMemorySize, PV_SMEM_BYTES);
        attr_done = true;
    }

    dim3 thr(256);

    // 0a) split inputs -> bf16 planes
    dim3 gSI(INELEM / (256 * 4), 1, 3);
    split_in_k<<<gSI, thr>>>(query, key_, value, dINh, dINl);

    // 0b) transpose + split W -> K-major bf16 planes
    dim3 gSW(DMODEL / 32, DMODEL / 32, 3);
    split_w_k<<<gSW, dim3(32, 8)>>>(Wq, Wk, Wv, dWh, dWl);

    // 1) Projections Q,K,V — bf16x3 + ldmatrix
    dim3 gP(DMODEL / 128, (BATCH * SEQ) / 128, 3);
    proj_qkv_k<<<gP, thr, BF3_SMEM_BYTES>>>(dINh, dINl, dWh, dWl,
                                            bq, bk, bv,
                                            dQh, dQl, dKh, dKl, dV);

    // 2) Scores — bf16x3 + ldmatrix
    dim3 gS(SEQ / 128, SEQ / 128, BATCH);
    scores_k<<<gS, thr, BF3_SMEM_BYTES>>>(dQh, dQl, dKh, dKl, dS);

    // 3) Softmax + threefry dropout; P pre-rounded tf32
    dim3 gSm(SEQ, BATCH, 1);
    softmax_dropout_k<<<gSm, thr>>>(dS);

    // 4) O = P @ Vt (conversion-free tf32 x1)
    dim3 gO(DMODEL / 128, SEQ / 128, BATCH);
    pv_k<<<gO, thr, PV_SMEM_BYTES>>>(dS, dV, out);
}